// round 12
// baseline (speedup 1.0000x reference)
#include <cuda_runtime.h>
#include <cuda_fp16.h>
#include <cstdint>
#include <math.h>

// ---------------------------------------------------------------------------
// Shapes: bs=4, H=16, DK=64, D=1024, n_w=128, n_v=1024
// Q/K projections: int8 IMMA m16n8k32, row-scaled 14-bit split (hi*128+lo),
//                  3 IMMAs per K=32 (hh + hi*lo + lo*hi).
// V3/V4/w1/out proj, cross, P.V: fp16 HMMA 1-term.
// Attention Q.K^T: fp16 3-term (Q,K stored as exact fp16 hi/lo pairs).
// ---------------------------------------------------------------------------

__device__ __forceinline__ uint32_t smem_u32(const void* p) {
    uint32_t a;
    asm("{ .reg .u64 t; cvta.to.shared.u64 t, %1; cvt.u32.u64 %0, t; }"
        : "=r"(a) : "l"(p));
    return a;
}

__device__ __forceinline__ void cp_async16(uint32_t dst, const void* src) {
    asm volatile("cp.async.cg.shared.global [%0], [%1], 16;"
                 :: "r"(dst), "l"(src) : "memory");
}
__device__ __forceinline__ void cp_commit() {
    asm volatile("cp.async.commit_group;" ::: "memory");
}
__device__ __forceinline__ void cp_wait0() {
    asm volatile("cp.async.wait_group 0;" ::: "memory");
}
__device__ __forceinline__ void cp_wait1() {
    asm volatile("cp.async.wait_group 1;" ::: "memory");
}

__device__ __forceinline__ void ldmatrix_x4(uint32_t* r, uint32_t addr) {
    asm volatile("ldmatrix.sync.aligned.m8n8.x4.shared.b16 {%0,%1,%2,%3}, [%4];"
                 : "=r"(r[0]), "=r"(r[1]), "=r"(r[2]), "=r"(r[3]) : "r"(addr));
}
__device__ __forceinline__ void ldmatrix_x2(uint32_t* r, uint32_t addr) {
    asm volatile("ldmatrix.sync.aligned.m8n8.x2.shared.b16 {%0,%1}, [%2];"
                 : "=r"(r[0]), "=r"(r[1]) : "r"(addr));
}
__device__ __forceinline__ void ldmatrix_x2_trans(uint32_t* r, uint32_t addr) {
    asm volatile("ldmatrix.sync.aligned.m8n8.x2.trans.shared.b16 {%0,%1}, [%2];"
                 : "=r"(r[0]), "=r"(r[1]) : "r"(addr));
}

__device__ __forceinline__ void mma_f16(float* c, const uint32_t* a, const uint32_t* b) {
    asm volatile(
        "mma.sync.aligned.m16n8k16.row.col.f32.f16.f16.f32 "
        "{%0,%1,%2,%3}, {%4,%5,%6,%7}, {%8,%9}, {%0,%1,%2,%3};"
        : "+f"(c[0]), "+f"(c[1]), "+f"(c[2]), "+f"(c[3])
        : "r"(a[0]), "r"(a[1]), "r"(a[2]), "r"(a[3]), "r"(b[0]), "r"(b[1]));
}

__device__ __forceinline__ void mma_s8(int* c, const uint32_t* a, const uint32_t* b) {
    asm volatile(
        "mma.sync.aligned.m16n8k32.row.col.s32.s8.s8.s32 "
        "{%0,%1,%2,%3}, {%4,%5,%6,%7}, {%8,%9}, {%0,%1,%2,%3};"
        : "+r"(c[0]), "+r"(c[1]), "+r"(c[2]), "+r"(c[3])
        : "r"(a[0]), "r"(a[1]), "r"(a[2]), "r"(a[3]), "r"(b[0]), "r"(b[1]));
}

// ----------------------------- scratch ------------------------------------
__device__ __align__(256) float g_S [4 * 16 * 128 * 1024];
__device__ __align__(256) float g_cr[4 * 16 * 1024];

__device__ __align__(256) __half g_Qh[4194304], g_Ql[4194304];
__device__ __align__(256) __half g_Kh[4194304], g_Kl[4194304];
__device__ __align__(256) __half g_V4h[4194304];
__device__ __align__(256) __half g_V3h[4194304];
__device__ __align__(256) __half g_W1h[524288];

__device__ __align__(256) __half g_Ahv[4194304];       // v_feat fp16 hi
__device__ __align__(256) __half g_Ahw[524288];        // w_feat fp16 hi
__device__ __align__(256) __half g_Wh[4 * 1048576];    // Wv3,Wv4,Ww1,Wout hi
__device__ __align__(256) __half g_Ch[4194304];        // ctx hi

// int8 path (Q/K projections)
__device__ __align__(256) int8_t g_A8h[4194304], g_A8l[4194304];
__device__ __align__(256) int8_t g_W8h[2097152], g_W8l[2097152];
__device__ __align__(256) float  g_sA[4096], g_sW[2048];

// ----------------------------- fp32 -> fp16 hi ----------------------------
__global__ void __launch_bounds__(256) conv_hi_kernel(
    const float* __restrict__ x, __half* __restrict__ hi, int n4)
{
    int i = blockIdx.x * 256 + threadIdx.x;
    if (i >= n4) return;
    float4 v = ((const float4*)x)[i];
    ((__half2*)hi)[2 * i]     = __floats2half2_rn(v.x, v.y);
    ((__half2*)hi)[2 * i + 1] = __floats2half2_rn(v.z, v.w);
}

__global__ void __launch_bounds__(256) conv4_hi_kernel(
    const float* __restrict__ p0, const float* __restrict__ p1,
    const float* __restrict__ p2, const float* __restrict__ p3,
    __half* __restrict__ hi)
{
    int i = blockIdx.x * 256 + threadIdx.x;
    int wsel = i >> 18;
    int j = i & 262143;
    const float* x = (wsel == 0) ? p0 : (wsel == 1) ? p1 : (wsel == 2) ? p2 : p3;
    float4 v = ((const float4*)x)[j];
    ((__half2*)hi)[2 * i]     = __floats2half2_rn(v.x, v.y);
    ((__half2*)hi)[2 * i + 1] = __floats2half2_rn(v.z, v.w);
}

// ----------------------------- int8 row quantization ----------------------
// x_row ~= s * (128*hi + lo), s = rowmax/16256, |hi|<=127, |lo|<=64
__device__ __forceinline__ void quant_row_body(
    const float* __restrict__ p, int8_t* __restrict__ hi,
    int8_t* __restrict__ lo, float* __restrict__ scale,
    int row, int t)
{
    float4 v = ((const float4*)p)[t];
    float mx = fmaxf(fmaxf(fabsf(v.x), fabsf(v.y)), fmaxf(fabsf(v.z), fabsf(v.w)));
#pragma unroll
    for (int o = 16; o; o >>= 1) mx = fmaxf(mx, __shfl_xor_sync(0xffffffffu, mx, o));
    __shared__ float red[8];
    if ((t & 31) == 0) red[t >> 5] = mx;
    __syncthreads();
    float m = red[0];
#pragma unroll
    for (int w = 1; w < 8; w++) m = fmaxf(m, red[w]);

    float inv = (m > 0.f) ? (16256.f / m) : 0.f;
    if (t == 0) scale[row] = m * (1.f / 16256.f);

    int q0 = __float2int_rn(v.x * inv);
    int q1 = __float2int_rn(v.y * inv);
    int q2 = __float2int_rn(v.z * inv);
    int q3 = __float2int_rn(v.w * inv);
    int h0 = __float2int_rn((float)q0 * (1.f / 128.f));
    int h1 = __float2int_rn((float)q1 * (1.f / 128.f));
    int h2 = __float2int_rn((float)q2 * (1.f / 128.f));
    int h3 = __float2int_rn((float)q3 * (1.f / 128.f));
    char4 hc = {(char)h0, (char)h1, (char)h2, (char)h3};
    char4 lc = {(char)(q0 - (h0 << 7)), (char)(q1 - (h1 << 7)),
                (char)(q2 - (h2 << 7)), (char)(q3 - (h3 << 7))};
    ((char4*)hi)[(size_t)row * 256 + t] = hc;
    ((char4*)lo)[(size_t)row * 256 + t] = lc;
}

__global__ void __launch_bounds__(256) quant_A(
    const float* __restrict__ x, int8_t* __restrict__ hi,
    int8_t* __restrict__ lo, float* __restrict__ scale)
{
    int row = blockIdx.x;
    quant_row_body(x + (size_t)row * 1024, hi, lo, scale, row, threadIdx.x);
}

__global__ void __launch_bounds__(256) quant_W2(
    const float* __restrict__ w0, const float* __restrict__ w1,
    int8_t* __restrict__ hi, int8_t* __restrict__ lo, float* __restrict__ scale)
{
    int row = blockIdx.x;
    const float* p = ((row >> 10) ? w1 : w0) + (size_t)(row & 1023) * 1024;
    quant_row_body(p, hi, lo, scale, row, threadIdx.x);
}

// ----------------------------- int8 IMMA Q/K GEMM --------------------------
// 64x128 tile, K-chunk 64 (2 x k32), double-buffered. grid (bn*2+wsel, bm)
static constexpr int QA_T = 64 * 80;      // int8 tile: 64 rows x 64B (+pad)
static constexpr int QW_T = 128 * 80;
static constexpr int QSTAGE = 2 * QA_T + 2 * QW_T;   // 30720
static constexpr int QSMEM  = 2 * QSTAGE;            // 61440

__global__ void __launch_bounds__(256, 2) imma_gemm_qk(
    const int8_t* __restrict__ A8h, const int8_t* __restrict__ A8l,
    const int8_t* __restrict__ W8h, const int8_t* __restrict__ W8l,
    const float* __restrict__ sA, const float* __restrict__ sW,
    const float* __restrict__ bv1, const float* __restrict__ bv2,
    __half* __restrict__ Qh, __half* __restrict__ Ql,
    __half* __restrict__ Kh, __half* __restrict__ Kl)
{
    extern __shared__ char smem[];
    const uint32_t sb = smem_u32(smem);
    int t = threadIdx.x;
    int lane = t & 31, wid = t >> 5;
    int wsel = blockIdx.x & 1;
    int bn = (blockIdx.x >> 1) * 128;
    int bm = blockIdx.y * 64;
    int wm = (wid & 1) * 32;
    int wn = (wid >> 1) * 32;

    const int8_t* Wh8 = W8h + (size_t)wsel * 1048576;
    const int8_t* Wl8 = W8l + (size_t)wsel * 1048576;

    int hh[2][4][4], mx[2][4][4];
#pragma unroll
    for (int i = 0; i < 2; i++)
#pragma unroll
        for (int j = 0; j < 4; j++)
#pragma unroll
            for (int k = 0; k < 4; k++) { hh[i][j][k] = 0; mx[i][j][k] = 0; }

    int ra = t >> 2, ca = t & 3;
    int rw1 = (t + 256) >> 2;

    auto stage_load = [&](int s, int k0) {
        uint32_t base = sb + s * QSTAGE;
        cp_async16(base + ra * 80 + ca * 16,
                   A8h + (size_t)(bm + ra) * 1024 + k0 + ca * 16);
        cp_async16(base + QA_T + ra * 80 + ca * 16,
                   A8l + (size_t)(bm + ra) * 1024 + k0 + ca * 16);
        uint32_t wb = base + 2 * QA_T;
        cp_async16(wb + ra  * 80 + ca * 16, Wh8 + (size_t)(bn + ra)  * 1024 + k0 + ca * 16);
        cp_async16(wb + rw1 * 80 + ca * 16, Wh8 + (size_t)(bn + rw1) * 1024 + k0 + ca * 16);
        uint32_t wlb = wb + QW_T;
        cp_async16(wlb + ra  * 80 + ca * 16, Wl8 + (size_t)(bn + ra)  * 1024 + k0 + ca * 16);
        cp_async16(wlb + rw1 * 80 + ca * 16, Wl8 + (size_t)(bn + rw1) * 1024 + k0 + ca * 16);
        cp_commit();
    };

    stage_load(0, 0);

    // b16-view lane addressing (identical frag layout to fp16 k16)
    int a_r = (lane & 15);
    int a_c = (lane >> 4) << 3;                       // b16 col 0/8
    int b4_r = (lane & 7) + ((lane >> 4) & 1) * 8;
    int b4_c = ((lane >> 3) & 1) << 3;

    for (int c = 0; c < 16; c++) {
        if (c + 1 < 16) {
            stage_load((c + 1) & 1, (c + 1) * 64);
            cp_wait1();
        } else {
            cp_wait0();
        }
        __syncthreads();

        uint32_t base = sb + (c & 1) * QSTAGE;
        uint32_t tAh = base, tAl = base + QA_T;
        uint32_t tWh = base + 2 * QA_T, tWl = tWh + QW_T;

#pragma unroll
        for (int kk = 0; kk < 32; kk += 16) {         // b16 units: 2 x k32
            uint32_t ah[2][4], al[2][4];
#pragma unroll
            for (int mt = 0; mt < 2; mt++) {
                uint32_t off = (uint32_t)((wm + mt * 16 + a_r) * 80 + (kk + a_c) * 2);
                ldmatrix_x4(ah[mt], tAh + off);
                ldmatrix_x4(al[mt], tAl + off);
            }
#pragma unroll
            for (int np = 0; np < 2; np++) {
                uint32_t off = (uint32_t)((wn + np * 16 + b4_r) * 80 + (kk + b4_c) * 2);
                uint32_t bh4[4], bl4[4];
                ldmatrix_x4(bh4, tWh + off);
                ldmatrix_x4(bl4, tWl + off);
                // hh term
                mma_s8(hh[0][2 * np + 0], ah[0], bh4 + 0);
                mma_s8(hh[0][2 * np + 1], ah[0], bh4 + 2);
                mma_s8(hh[1][2 * np + 0], ah[1], bh4 + 0);
                mma_s8(hh[1][2 * np + 1], ah[1], bh4 + 2);
                // mix: hi*lo
                mma_s8(mx[0][2 * np + 0], ah[0], bl4 + 0);
                mma_s8(mx[0][2 * np + 1], ah[0], bl4 + 2);
                mma_s8(mx[1][2 * np + 0], ah[1], bl4 + 0);
                mma_s8(mx[1][2 * np + 1], ah[1], bl4 + 2);
                // mix: lo*hi
                mma_s8(mx[0][2 * np + 0], al[0], bh4 + 0);
                mma_s8(mx[0][2 * np + 1], al[0], bh4 + 2);
                mma_s8(mx[1][2 * np + 0], al[1], bh4 + 0);
                mma_s8(mx[1][2 * np + 1], al[1], bh4 + 2);
            }
        }
        __syncthreads();
    }

    // epilogue: val = sA[row]*sW[col]*(16384*hh + 128*mx) + bias; fp16 pair
    const float* bias = wsel ? bv2 : bv1;
    __half* outh = wsel ? Kh : Qh;
    __half* outl = wsel ? Kl : Ql;
    const float* sWb = sW + (size_t)wsel * 1024;
#pragma unroll
    for (int mt = 0; mt < 2; mt++) {
        int row_a = bm + wm + mt * 16 + (lane >> 2);
#pragma unroll
        for (int rr = 0; rr < 2; rr++) {
            int row = row_a + rr * 8;
            float sa = sA[row];
            int b = row >> 10, ii = row & 1023;
#pragma unroll
            for (int nt = 0; nt < 4; nt++) {
                int o = bn + wn + nt * 8 + (lane & 3) * 2;
                float sw0 = sWb[o] * sa, sw1 = sWb[o + 1] * sa;
                float vx = sw0 * (16384.f * (float)hh[mt][nt][rr * 2 + 0]
                                 + 128.f * (float)mx[mt][nt][rr * 2 + 0]) + bias[o];
                float vy = sw1 * (16384.f * (float)hh[mt][nt][rr * 2 + 1]
                                 + 128.f * (float)mx[mt][nt][rr * 2 + 1]) + bias[o + 1];
                int h = o >> 6, d = o & 63;
                size_t idx = ((((size_t)(b * 16 + h) << 10) + (size_t)ii << 6) + (size_t)d) >> 1;
                __half hx = __float2half_rn(vx), hy = __float2half_rn(vy);
                __half lx = __float2half_rn(vx - __half2float(hx));
                __half ly = __float2half_rn(vy - __half2float(hy));
                ((__half2*)outh)[idx] = __half2{hx, hy};
                ((__half2*)outl)[idx] = __half2{lx, ly};
            }
        }
    }
}

// ----------------------------- fp16 HMMA 1-term GEMM -----------------------
static constexpr int A_T = 64 * 80;
static constexpr int W_T = 128 * 80;
static constexpr int STAGE1 = A_T + W_T;
static constexpr int SMEM1 = 2 * STAGE1;   // 30720

__device__ __forceinline__ void gemm_mainloop64_1(
    const __half* __restrict__ Ah, const __half* __restrict__ Wh,
    uint32_t sb, int bm, int bn, int t, float acc[2][4][4])
{
    int lane = t & 31, wid = t >> 5;
    int wm = (wid & 1) * 32;
    int wn = (wid >> 1) * 32;

    int ra = t >> 2, ca = t & 3;
    int rw1 = (t + 256) >> 2;

    auto stage_load = [&](int s, int k0) {
        uint32_t base = sb + s * STAGE1;
        cp_async16(base + ra * 80 + ca * 16, Ah + (size_t)(bm + ra) * 1024 + k0 + ca * 8);
        uint32_t wb = base + A_T;
        cp_async16(wb + ra  * 80 + ca * 16, Wh + (size_t)(bn + ra)  * 1024 + k0 + ca * 8);
        cp_async16(wb + rw1 * 80 + ca * 16, Wh + (size_t)(bn + rw1) * 1024 + k0 + ca * 8);
        cp_commit();
    };

    stage_load(0, 0);

    int a_r = (lane & 15);
    int a_c = (lane >> 4) << 3;
    int b4_r = (lane & 7) + ((lane >> 4) & 1) * 8;
    int b4_c = ((lane >> 3) & 1) << 3;

    for (int c = 0; c < 32; c++) {
        if (c + 1 < 32) {
            stage_load((c + 1) & 1, (c + 1) * 32);
            cp_wait1();
        } else {
            cp_wait0();
        }
        __syncthreads();

        uint32_t base = sb + (c & 1) * STAGE1;
        uint32_t tAh = base, tWh = base + A_T;

#pragma unroll
        for (int kk = 0; kk < 32; kk += 16) {
            uint32_t ah[2][4];
#pragma unroll
            for (int mt = 0; mt < 2; mt++) {
                uint32_t off = (uint32_t)((wm + mt * 16 + a_r) * 80 + (kk + a_c) * 2);
                ldmatrix_x4(ah[mt], tAh + off);
            }
#pragma unroll
            for (int np = 0; np < 2; np++) {
                uint32_t off = (uint32_t)((wn + np * 16 + b4_r) * 80 + (kk + b4_c) * 2);
                uint32_t bh4[4];
                ldmatrix_x4(bh4, tWh + off);
                mma_f16(acc[0][2 * np + 0], ah[0], bh4 + 0);
                mma_f16(acc[0][2 * np + 1], ah[0], bh4 + 2);
                mma_f16(acc[1][2 * np + 0], ah[1], bh4 + 0);
                mma_f16(acc[1][2 * np + 1], ah[1], bh4 + 2);
            }
        }
        __syncthreads();
    }
}

__device__ __forceinline__ void epi_head_hi(
    float acc[2][4][4], const float* bias, __half* outh,
    int bm, int bn, int t, int n_per_b)
{
    int lane = t & 31, wid = t >> 5;
    int wm = (wid & 1) * 32, wn = (wid >> 1) * 32;
#pragma unroll
    for (int mt = 0; mt < 2; mt++) {
        int row_a = bm + wm + mt * 16 + (lane >> 2);
#pragma unroll
        for (int rr = 0; rr < 2; rr++) {
            int row = row_a + rr * 8;
            int b = row / n_per_b, ii = row % n_per_b;
#pragma unroll
            for (int nt = 0; nt < 4; nt++) {
                int o = bn + wn + nt * 8 + (lane & 3) * 2;
                float vx = acc[mt][nt][rr * 2 + 0] + bias[o];
                float vy = acc[mt][nt][rr * 2 + 1] + bias[o + 1];
                int h = o >> 6, d = o & 63;
                size_t idx = ((((size_t)(b * 16 + h) * n_per_b + ii) << 6) + (size_t)d) >> 1;
                ((__half2*)outh)[idx] =
                    __half2{__float2half_rn(vx), __float2half_rn(vy)};
            }
        }
    }
}

// V3/V4 projections (1-term): grid (bn*2+wsel, bm)
__global__ void __launch_bounds__(256, 3) hmma_gemm_v34(
    const __half* __restrict__ Ah, const __half* __restrict__ WhB,
    const float* __restrict__ bv3, const float* __restrict__ bv4,
    __half* __restrict__ V3h, __half* __restrict__ V4h)
{
    extern __shared__ char smem[];
    const uint32_t sb = smem_u32(smem);
    int t = threadIdx.x;
    int wsel = blockIdx.x & 1;
    int bn = (blockIdx.x >> 1) * 128;
    int bm = blockIdx.y * 64;

    float acc[2][4][4];
#pragma unroll
    for (int i = 0; i < 2; i++)
#pragma unroll
        for (int j = 0; j < 4; j++)
#pragma unroll
            for (int k = 0; k < 4; k++) acc[i][j][k] = 0.f;

    const __half* Wh = WhB + (size_t)wsel * 1048576;   // slot0=Wv3, slot1=Wv4
    gemm_mainloop64_1(Ah, Wh, sb, bm, bn, t, acc);
    if (wsel == 0) epi_head_hi(acc, bv3, V3h, bm, bn, t, 1024);
    else           epi_head_hi(acc, bv4, V4h, bm, bn, t, 1024);
}

__global__ void __launch_bounds__(256, 3) hmma_gemm_w1(
    const __half* __restrict__ Ah, const __half* __restrict__ Wh,
    const float* __restrict__ bias, __half* __restrict__ W1h)
{
    extern __shared__ char smem[];
    const uint32_t sb = smem_u32(smem);
    int t = threadIdx.x;
    int bn = blockIdx.x * 128, bm = blockIdx.y * 64;
    float acc[2][4][4];
#pragma unroll
    for (int i = 0; i < 2; i++)
#pragma unroll
        for (int j = 0; j < 4; j++)
#pragma unroll
            for (int k = 0; k < 4; k++) acc[i][j][k] = 0.f;
    gemm_mainloop64_1(Ah, Wh, sb, bm, bn, t, acc);
    epi_head_hi(acc, bias, W1h, bm, bn, t, 128);
}

__global__ void __launch_bounds__(256, 3) hmma_gemm_out(
    const __half* __restrict__ Ah, const __half* __restrict__ Wh,
    const float* __restrict__ bias, float* __restrict__ outf)
{
    extern __shared__ char smem[];
    const uint32_t sb = smem_u32(smem);
    int t = threadIdx.x;
    int bn = blockIdx.x * 128, bm = blockIdx.y * 64;
    float acc[2][4][4];
#pragma unroll
    for (int i = 0; i < 2; i++)
#pragma unroll
        for (int j = 0; j < 4; j++)
#pragma unroll
            for (int k = 0; k < 4; k++) acc[i][j][k] = 0.f;
    gemm_mainloop64_1(Ah, Wh, sb, bm, bn, t, acc);

    int lane = t & 31, wid = t >> 5;
    int wm = (wid & 1) * 32, wn = (wid >> 1) * 32;
#pragma unroll
    for (int mt = 0; mt < 2; mt++) {
        int row_a = bm + wm + mt * 16 + (lane >> 2);
#pragma unroll
        for (int rr = 0; rr < 2; rr++) {
            int row = row_a + rr * 8;
#pragma unroll
            for (int nt = 0; nt < 4; nt++) {
                int o = bn + wn + nt * 8 + (lane & 3) * 2;
                float vx = acc[mt][nt][rr * 2 + 0] + bias[o];
                float vy = acc[mt][nt][rr * 2 + 1] + bias[o + 1];
                *(float2*)&outf[(size_t)row * 1024 + o] = float2{vx, vy};
            }
        }
    }
}

// ---------------------------------------------------------------------------
// HMMA cross scores (1-term), one-shot K=64
// ---------------------------------------------------------------------------
static constexpr int XPITCH = 144;
static constexpr int X_T = 128 * XPITCH;
static constexpr int XS_SMEM = 2 * X_T;

__global__ void __launch_bounds__(256) cross_scores_hmma(
    const __half* __restrict__ W1h,
    const __half* __restrict__ V3h, float* __restrict__ S)
{
    extern __shared__ char smem[];
    const uint32_t sb = smem_u32(smem);
    int t = threadIdx.x, lane = t & 31, wid = t >> 5;
    int vt = blockIdx.x, bh = blockIdx.y;

    const __half* a_h = W1h + (size_t)bh * 8192;
    const __half* b_h = V3h + (size_t)bh * 65536 + (size_t)vt * 8192;

#pragma unroll
    for (int it = 0; it < 4; it++) {
        int ch = t + it * 256;
        int row = ch >> 3, cc = ch & 7;
        size_t g = (size_t)row * 64 + cc * 8;
        uint32_t d = (uint32_t)(row * XPITCH + cc * 16);
        cp_async16(sb + 0 * X_T + d, a_h + g);
        cp_async16(sb + 1 * X_T + d, b_h + g);
    }
    cp_commit();
    cp_wait0();
    __syncthreads();

    int wm = (wid & 1) * 64, wn = (wid >> 1) * 32;
    int a_r = lane & 15, a_c = (lane >> 4) << 3;
    int b4_r = (lane & 7) + ((lane >> 4) & 1) * 8;
    int b4_c = ((lane >> 3) & 1) << 3;

    float acc[4][4][4];
#pragma unroll
    for (int i = 0; i < 4; i++)
#pragma unroll
        for (int j = 0; j < 4; j++)
#pragma unroll
            for (int k = 0; k < 4; k++) acc[i][j][k] = 0.f;

#pragma unroll
    for (int ks = 0; ks < 4; ks++) {
        uint32_t ah[4][4];
#pragma unroll
        for (int mt = 0; mt < 4; mt++) {
            uint32_t off = (uint32_t)((wm + mt * 16 + a_r) * XPITCH + (ks * 16 + a_c) * 2);
            ldmatrix_x4(ah[mt], sb + 0 * X_T + off);
        }
#pragma unroll
        for (int np = 0; np < 2; np++) {
            uint32_t off = (uint32_t)((wn + np * 16 + b4_r) * XPITCH + (ks * 16 + b4_c) * 2);
            uint32_t bh4[4];
            ldmatrix_x4(bh4, sb + 1 * X_T + off);
#pragma unroll
            for (int mt = 0; mt < 4; mt++) {
                mma_f16(acc[mt][2 * np + 0], ah[mt], bh4 + 0);
                mma_f16(acc[mt][2 * np + 1], ah[mt], bh4 + 2);
            }
        }
    }

    float* Sb = S + (size_t)bh * 131072;
#pragma unroll
    for (int mt = 0; mt < 4; mt++) {
        int row_a = wm + mt * 16 + (lane >> 2);
#pragma unroll
        for (int rr = 0; rr < 2; rr++) {
            int w = row_a + rr * 8;
#pragma unroll
            for (int nt = 0; nt < 4; nt++) {
                int v = vt * 128 + wn + nt * 8 + (lane & 3) * 2;
                *(float2*)&Sb[(size_t)w * 1024 + v] =
                    float2{acc[mt][nt][rr * 2 + 0], acc[mt][nt][rr * 2 + 1]};
            }
        }
    }
}

// ---------------------------------------------------------------------------
// Fused softmax + column-sum
// ---------------------------------------------------------------------------
__global__ void __launch_bounds__(256) cross_softsum(
    const float* __restrict__ S, float* __restrict__ cross)
{
    int bh = blockIdx.x;
    int t = threadIdx.x, lane = t & 31, w = t >> 5;
    __shared__ float sm[128], siv[128];
    const float* Sb = S + (size_t)bh * 131072;

    for (int r = w; r < 128; r += 8) {
        const float4* p = (const float4*)(Sb + (size_t)r * 1024);
        float mx = -1e30f;
#pragma unroll
        for (int j = 0; j < 8; j++) {
            float4 v = p[lane + j * 32];
            mx = fmaxf(fmaxf(mx, fmaxf(v.x, v.y)), fmaxf(v.z, v.w));
        }
#pragma unroll
        for (int o = 16; o; o >>= 1) mx = fmaxf(mx, __shfl_xor_sync(0xffffffffu, mx, o));
        float sum = 0.f;
#pragma unroll
        for (int j = 0; j < 8; j++) {
            float4 v = p[lane + j * 32];
            sum += __expf(v.x - mx) + __expf(v.y - mx)
                 + __expf(v.z - mx) + __expf(v.w - mx);
        }
#pragma unroll
        for (int o = 16; o; o >>= 1) sum += __shfl_xor_sync(0xffffffffu, sum, o);
        if (lane == 0) { sm[r] = mx; siv[r] = 1.f / sum; }
    }
    __syncthreads();

    float a0 = 0.f, a1 = 0.f, a2 = 0.f, a3 = 0.f;
    int cb = t * 4;
    for (int r = 0; r < 128; r++) {
        float m = sm[r], iv = siv[r];
        float4 v = *(const float4*)(Sb + (size_t)r * 1024 + cb);
        a0 += __expf(v.x - m) * iv;
        a1 += __expf(v.y - m) * iv;
        a2 += __expf(v.z - m) * iv;
        a3 += __expf(v.w - m) * iv;
    }
    *(float4*)(cross + (size_t)bh * 1024 + cb) = float4{a0, a1, a2, a3};
}

// ---------------------------------------------------------------------------
// HMMA flash self-attention: QK 3-term, PV 1-term; 2 CTAs/SM.
// ---------------------------------------------------------------------------
static constexpr int APITCH = 144;
static constexpr int AQ_BYTES  = 128 * APITCH;
static constexpr int AKV_T     = 64 * APITCH;
static constexpr int AKV_BUF   = 3 * AKV_T + 256;
static constexpr int AKV_BASE  = 2 * AQ_BYTES;
static constexpr int ATTN_SMEM = AKV_BASE + 2 * AKV_BUF;

__global__ void __launch_bounds__(256, 2) attn_hmma(
    const __half* __restrict__ Qh_g, const __half* __restrict__ Ql_g,
    const __half* __restrict__ Kh_g, const __half* __restrict__ Kl_g,
    const __half* __restrict__ Vh_g,
    const float* __restrict__ cross,
    __half* __restrict__ Ch)
{
    extern __shared__ char smem[];
    const uint32_t sb = smem_u32(smem);
    int t = threadIdx.x;
    int lane = t & 31, w = t >> 5;
    int bh = blockIdx.y, qt = blockIdx.x;
    int b = bh >> 4, h = bh & 15;

    const __half* qh_g = Qh_g + (size_t)bh * 65536 + (size_t)qt * 8192;
    const __half* ql_g = Ql_g + (size_t)bh * 65536 + (size_t)qt * 8192;
    const __half* kh_g = Kh_g + (size_t)bh * 65536;
    const __half* kl_g = Kl_g + (size_t)bh * 65536;
    const __half* vh_g = Vh_g + (size_t)bh * 65536;
    const float* cr = cross + (size_t)bh * 1024;

    {
#pragma unroll
        for (int it = 0; it < 4; it++) {
            int ch = t + it * 256;
            int row = ch >> 3, cc = ch & 7;
            cp_async16(sb + row * APITCH + cc * 16, qh_g + (size_t)row * 64 + cc * 8);
            cp_async16(sb + AQ_BYTES + row * APITCH + cc * 16,
                       ql_g + (size_t)row * 64 + cc * 8);
        }
    }

    auto stage_kv = [&](int s, int kb) {
        uint32_t base = sb + AKV_BASE + s * AKV_BUF;
        int krow0 = kb * 64;
#pragma unroll
        for (int it = 0; it < 2; it++) {
            int ch = t + it * 256;
            int row = ch >> 3, cc = ch & 7;
            size_t g = (size_t)(krow0 + row) * 64 + cc * 8;
            uint32_t d = base + row * APITCH + cc * 16;
            cp_async16(d + 0 * AKV_T, kh_g + g);
            cp_async16(d + 1 * AKV_T, kl_g + g);
            cp_async16(d + 2 * AKV_T, vh_g + g);
        }
        if (t < 16) cp_async16(base + 3 * AKV_T + t * 16, cr + kb * 64 + t * 4);
        cp_commit();
    };

    stage_kv(0, 0);
    cp_wait0();
    __syncthreads();

    uint32_t qh[4][4], ql[4][4];
    {
        int a_r = w * 16 + (lane & 15);
        int a_c = (lane >> 4) << 3;
#pragma unroll
        for (int ks = 0; ks < 4; ks++) {
            uint32_t off = (uint32_t)(a_r * APITCH + (ks * 16 + a_c) * 2);
            ldmatrix_x4(qh[ks], sb + off);
            ldmatrix_x4(ql[ks], sb + AQ_BYTES + off);
        }
    }

    float o[8][4];
#pragma unroll
    for (int i = 0; i < 8; i++)
#pragma unroll
        for (int j = 0; j < 4; j++) o[i][j] = 0.f;
    float m0 = -1e30f, m1 = -1e30f, l0 = 0.f, l1 = 0.f;

    int c2 = (lane & 3) * 2;
    int kb_r = lane & 7;
    int kb_c = ((lane >> 3) & 1) << 3;

    for (int kb = 0; kb < 16; kb++) {
        if (kb + 1 < 16) stage_kv((kb + 1) & 1, kb + 1);

        uint32_t kvb = sb + AKV_BASE + (kb & 1) * AKV_BUF;
        const float* crs = (const float*)(smem + AKV_BASE + (kb & 1) * AKV_BUF + 3 * AKV_T);

        float s[8][4];
#pragma unroll
        for (int nt = 0; nt < 8; nt++) {
            float b0 = crs[nt * 8 + c2];
            float b1 = crs[nt * 8 + c2 + 1];
            s[nt][0] = b0; s[nt][1] = b1; s[nt][2] = b0; s[nt][3] = b1;
        }

#pragma unroll
        for (int ks = 0; ks < 4; ks++) {
#pragma unroll
            for (int ntp = 0; ntp < 4; ntp++) {
                int nt0 = 2 * ntp, nt1 = nt0 + 1;
                uint32_t off0 = (uint32_t)((nt0 * 8 + kb_r) * APITCH + (ks * 16 + kb_c) * 2);
                uint32_t off1 = (uint32_t)((nt1 * 8 + kb_r) * APITCH + (ks * 16 + kb_c) * 2);
                uint32_t kh0[2], kl0[2], kh1[2], kl1[2];
                ldmatrix_x2(kh0, kvb + off0);
                ldmatrix_x2(kh1, kvb + off1);
                ldmatrix_x2(kl0, kvb + AKV_T + off0);
                ldmatrix_x2(kl1, kvb + AKV_T + off1);
                mma_f16(s[nt0], qh[ks], kh0);
                mma_f16(s[nt1], qh[ks], kh1);
                mma_f16(s[nt0], qh[ks], kl0);
                mma_f16(s[nt1], qh[ks], kl1);
                mma_f16(s[nt0], ql[ks], kh0);
                mma_f16(s[nt1], ql[ks], kh1);
            }
        }

        float mx0 = -1e30f, mx1 = -1e30f;
#pragma unroll
        for (int nt = 0; nt < 8; nt++) {
            mx0 = fmaxf(mx0, fmaxf(s[nt][0], s[nt][1]));
            mx1 = fmaxf(mx1, fmaxf(s[nt][2], s[nt][3]));
        }
        mx0 = fmaxf(mx0, __shfl_xor_sync(0xffffffffu, mx0, 1));
        mx0 = fmaxf(mx0, __shfl_xor_sync(0xffffffffu, mx0, 2));
        mx1 = fmaxf(mx1, __shfl_xor_sync(0xffffffffu, mx1, 1));
        mx1 = fmaxf(mx1, __shfl_xor_sync(0xffffffffu, mx1, 2));
        float mn0 = fmaxf(m0, mx0), mn1 = fmaxf(m1, mx1);
        float sc0 = __expf(m0 - mn0), sc1 = __expf(m1 - mn1);
        m0 = mn0; m1 = mn1;

        float rs0 = 0.f, rs1 = 0.f;
        uint32_t ph0[8], ph1[8];
#pragma unroll
        for (int nt = 0; nt < 8; nt++) {
            float p0 = __expf(s[nt][0] - mn0);
            float p1 = __expf(s[nt][1] - mn0);
            float p2 = __expf(s[nt][2] - mn1);
            float p3 = __expf(s[nt][3] - mn1);
            rs0 += p0 + p1; rs1 += p2 + p3;
            __half2 hA = __floats2half2_rn(p0, p1);
            __half2 hB = __floats2half2_rn(p2, p3);
            ph0[nt] = *(uint32_t*)&hA;
            ph1[nt] = *(uint32_t*)&hB;
        }
        rs0 += __shfl_xor_sync(0xffffffffu, rs0, 1);
        rs0 += __shfl_xor_sync(0xffffffffu, rs0, 2);
        rs1 += __shfl_xor_sync(0xffffffffu, rs1, 1);
        rs1 += __shfl_xor_sync(0xffffffffu, rs1, 2);
        l0 = l0 * sc0 + rs0;
        l1 = l1 * sc1 + rs1;
#pragma unroll
        for (int nt = 0; nt < 8; nt++) {
            o[nt][0] *= sc0; o[nt][1] *= sc0;
            o[nt][2] *= sc1; o[nt][3] *= sc1;
        }

        int v_r = (lane & 7) + ((lane >> 3) & 1) * 8;
#pragma unroll
        for (int kt = 0; kt < 4; kt++) {
            uint32_t ah[4] = {ph0[2 * kt], ph1[2 * kt], ph0[2 * kt + 1], ph1[2 * kt + 1]};
#pragma unroll
            for (int ntp = 0; ntp < 4; ntp++) {
                int nt0 = 2 * ntp, nt1 = nt0 + 1;
                uint32_t voff0 = (uint32_t)((kt * 16 + v_r) * APITCH + nt0 * 16);
                uint32_t voff1 = (uint32_t)((kt * 16 + v_r) * APITCH + nt1 * 16);
                uint32_t vh0[2], vh1[2];
                ldmatrix_x2_trans(vh0, kvb + 2 * AKV_T + voff0);
                ldmatrix_x2_trans(vh1, kvb + 2 * AKV_T + voff1);
                mma_f16(o[nt0], ah, vh0);
                mma_f16(o[nt1], ah, vh1);
            }
        }

        if (kb + 1 < 16) {
            cp_wait0();
            __syncthreads();
        }
    }

    float inv0 = 1.f / l0, inv1 = 1.f / l1;
    int row0 = qt * 128 + w * 16 + (lane >> 2);
    __half2* Ch2 = (__half2*)Ch;
#pragma unroll
    for (int nt = 0; nt < 8; nt++) {
        int d = nt * 8 + c2;
        {
            float x0 = o[nt][0] * inv0, x1 = o[nt][1] * inv0;
            size_t idx = (((size_t)b * 1024 + row0) * 1024 + h * 64 + d) >> 1;
            Ch2[idx] = __floats2half2_rn(x0, x1);
        }
        {
            float x0 = o[nt][2] * inv1, x1 = o[nt][3] * inv1;
            size_t idx = (((size_t)b * 1024 + row0 + 8) * 1024 + h * 64 + d) >> 1;
            Ch2[idx] = __floats2half2_rn(x0, x1);
        }
    }
}

// ---------------------------------------------------------------------------
// Launch (idx 3 = imma_gemm_qk -> ncu profiles it)
// ---------------------------------------------------------------------------
extern "C" void kernel_launch(void* const* d_in, const int* in_sizes, int n_in,
                              void* d_out, int out_size)
{
    const float* w_feat = (const float*)d_in[0];
    const float* v_feat = (const float*)d_in[1];
    const float* Ww1  = (const float*)d_in[2];
    const float* bw1  = (const float*)d_in[3];
    const float* Wv1  = (const float*)d_in[4];
    const float* bv1  = (const float*)d_in[5];
    const float* Wv2  = (const float*)d_in[6];
    const float* bv2  = (const float*)d_in[7];
    const float* Wv3  = (const float*)d_in[8];
    const float* bv3  = (const float*)d_in[9];
    const float* Wv4  = (const float*)d_in[10];
    const float* bv4  = (const float*)d_in[11];
    const float* Wout = (const float*)d_in[12];
    const float* bout = (const float*)d_in[13];
    float* out = (float*)d_out;

    float *Sp, *crp, *sAp, *sWp;
    cudaGetSymbolAddress((void**)&Sp,  g_S);
    cudaGetSymbolAddress((void**)&crp, g_cr);
    cudaGetSymbolAddress((void**)&sAp, g_sA);
    cudaGetSymbolAddress((void**)&sWp, g_sW);

    __half *Qh, *Ql, *Kh, *Kl, *V4h, *V3h, *W1h;
    cudaGetSymbolAddress((void**)&Qh,  g_Qh);
    cudaGetSymbolAddress((void**)&Ql,  g_Ql);
    cudaGetSymbolAddress((void**)&Kh,  g_Kh);
    cudaGetSymbolAddress((void**)&Kl,  g_Kl);
    cudaGetSymbolAddress((void**)&V4h, g_V4h);
    cudaGetSymbolAddress((void**)&V3h, g_V3h);
    cudaGetSymbolAddress((void**)&W1h, g_W1h);

    __half *Ahv, *Ahw, *Whp, *Chp;
    cudaGetSymbolAddress((void**)&Ahv, g_Ahv);
    cudaGetSymbolAddress((void**)&Ahw, g_Ahw);
    cudaGetSymbolAddress((void**)&Whp, g_Wh);
    cudaGetSymbolAddress((void**)&Chp, g_Ch);

    int8_t *A8h, *A8l, *W8h, *W8l;
    cudaGetSymbolAddress((void**)&A8h, g_A8h);
    cudaGetSymbolAddress((void**)&A8l, g_A8l);
    cudaGetSymbolAddress((void**)&W8h, g_W8h);
    cudaGetSymbolAddress((void**)&W8l, g_W8l);

    cudaFuncSetAttribute(imma_gemm_qk, cudaFuncAttributeMaxDynamicSharedMemorySize, QSMEM);
    cudaFuncSetAttribute(hmma_gemm_v34, cudaFuncAttributeMaxDynamicSharedMemorySize, SMEM1);
    cudaFuncSetAttribute(hmma_gemm_w1, cudaFuncAttributeMaxDynamicSharedMemorySize, SMEM1);
    cudaFuncSetAttribute(hmma_gemm_out, cudaFuncAttributeMaxDynamicSharedMemorySize, SMEM1);
    cudaFuncSetAttribute(cross_scores_hmma, cudaFuncAttributeMaxDynamicSharedMemorySize, XS_SMEM);
    cudaFuncSetAttribute(attn_hmma, cudaFuncAttributeMaxDynamicSharedMemorySize, ATTN_SMEM);

    // idx 0..2: conversions + quantization needed by Q/K GEMM
    conv_hi_kernel<<<4096, 256>>>(v_feat, Ahv, 1048576);        // 0
    quant_A<<<4096, 256>>>(v_feat, A8h, A8l, sAp);              // 1
    quant_W2<<<2048, 256>>>(Wv1, Wv2, W8h, W8l, sWp);           // 2

    // idx 3: int8 Q/K projections  <-- ncu target
    imma_gemm_qk<<<dim3(16, 64), 256, QSMEM>>>(
        A8h, A8l, W8h, W8l, sAp, sWp, bv1, bv2, Qh, Ql, Kh, Kl); // 3

    // remaining weights (fp16 hi only: Wv3, Wv4, Ww1, Wout)
    conv4_hi_kernel<<<4096, 256>>>(Wv3, Wv4, Ww1, Wout, Whp);    // 4
    hmma_gemm_v34<<<dim3(16, 64), 256, SMEM1>>>(
        Ahv, Whp, bv3, bv4, V3h, V4h);                           // 5

    conv_hi_kernel<<<512, 256>>>(w_feat, Ahw, 131072);           // 6
    hmma_gemm_w1<<<dim3(8, 8), 256, SMEM1>>>(
        Ahw, Whp + 2ull * 1048576, bw1, W1h);                    // 7

    cross_scores_hmma<<<dim3(8, 64), 256, XS_SMEM>>>(W1h, V3h, Sp);  // 8
    cross_softsum<<<64, 256>>>(Sp, crp);                             // 9

    attn_hmma<<<dim3(8, 64), 256, ATTN_SMEM>>>(Qh, Ql, Kh, Kl, V4h, crp, Chp); // 10

    hmma_gemm_out<<<dim3(8, 64), 256, SMEM1>>>(
        Chp, Whp + 3ull * 1048576, bout, out);                   // 11
}

// round 13
// speedup vs baseline: 1.4494x; 1.4494x over previous
#include <cuda_runtime.h>
#include <cuda_fp16.h>
#include <cstdint>
#include <math.h>

// ---------------------------------------------------------------------------
// Shapes: bs=4, H=16, DK=64, D=1024, n_w=128, n_v=1024
// HMMA fp16, calibrated error compensation:
//   3-term (AhWh+AhWl+AlWh): Q/K projections, Q.K^T   (score path: mandatory)
//   1-term (AhWh):           V3/V4/w1 proj, cross, P.V, out proj
// GEMM tiles 128x128 (best measured per-unit efficiency), 2 CTAs/SM.
// Attention: x4 LDSM for K-pairs and V-pairs.
// ---------------------------------------------------------------------------

__device__ __forceinline__ uint32_t smem_u32(const void* p) {
    uint32_t a;
    asm("{ .reg .u64 t; cvta.to.shared.u64 t, %1; cvt.u32.u64 %0, t; }"
        : "=r"(a) : "l"(p));
    return a;
}

__device__ __forceinline__ void cp_async16(uint32_t dst, const void* src) {
    asm volatile("cp.async.cg.shared.global [%0], [%1], 16;"
                 :: "r"(dst), "l"(src) : "memory");
}
__device__ __forceinline__ void cp_commit() {
    asm volatile("cp.async.commit_group;" ::: "memory");
}
__device__ __forceinline__ void cp_wait0() {
    asm volatile("cp.async.wait_group 0;" ::: "memory");
}
__device__ __forceinline__ void cp_wait1() {
    asm volatile("cp.async.wait_group 1;" ::: "memory");
}

__device__ __forceinline__ void ldmatrix_x4(uint32_t* r, uint32_t addr) {
    asm volatile("ldmatrix.sync.aligned.m8n8.x4.shared.b16 {%0,%1,%2,%3}, [%4];"
                 : "=r"(r[0]), "=r"(r[1]), "=r"(r[2]), "=r"(r[3]) : "r"(addr));
}
__device__ __forceinline__ void ldmatrix_x4_trans(uint32_t* r, uint32_t addr) {
    asm volatile("ldmatrix.sync.aligned.m8n8.x4.trans.shared.b16 {%0,%1,%2,%3}, [%4];"
                 : "=r"(r[0]), "=r"(r[1]), "=r"(r[2]), "=r"(r[3]) : "r"(addr));
}

__device__ __forceinline__ void mma_f16(float* c, const uint32_t* a, const uint32_t* b) {
    asm volatile(
        "mma.sync.aligned.m16n8k16.row.col.f32.f16.f16.f32 "
        "{%0,%1,%2,%3}, {%4,%5,%6,%7}, {%8,%9}, {%0,%1,%2,%3};"
        : "+f"(c[0]), "+f"(c[1]), "+f"(c[2]), "+f"(c[3])
        : "r"(a[0]), "r"(a[1]), "r"(a[2]), "r"(a[3]), "r"(b[0]), "r"(b[1]));
}

// ----------------------------- scratch ------------------------------------
__device__ __align__(256) float g_S [4 * 16 * 128 * 1024];
__device__ __align__(256) float g_cr[4 * 16 * 1024];

__device__ __align__(256) __half g_Qh[4194304], g_Ql[4194304];
__device__ __align__(256) __half g_Kh[4194304], g_Kl[4194304];
__device__ __align__(256) __half g_V4h[4194304];
__device__ __align__(256) __half g_V3h[4194304];
__device__ __align__(256) __half g_W1h[524288];

__device__ __align__(256) __half g_Ahv[4194304], g_Alv[4194304];
__device__ __align__(256) __half g_Ahw[524288];
__device__ __align__(256) __half g_Wh[6 * 1048576], g_Wl[2 * 1048576];
__device__ __align__(256) __half g_Ch[4194304];

// ----------------------------- fp32 -> fp16 conversions --------------------
__device__ __forceinline__ void split4f(float4 v, __half2& h01, __half2& h23,
                                        __half2& l01, __half2& l23)
{
    __half h0 = __float2half_rn(v.x), h1 = __float2half_rn(v.y);
    __half h2 = __float2half_rn(v.z), h3 = __float2half_rn(v.w);
    __half l0 = __float2half_rn(v.x - __half2float(h0));
    __half l1 = __float2half_rn(v.y - __half2float(h1));
    __half l2 = __float2half_rn(v.z - __half2float(h2));
    __half l3 = __float2half_rn(v.w - __half2float(h3));
    h01 = __half2{h0, h1}; h23 = __half2{h2, h3};
    l01 = __half2{l0, l1}; l23 = __half2{l2, l3};
}

__global__ void __launch_bounds__(256) split_kernel(
    const float* __restrict__ x, __half* __restrict__ hi,
    __half* __restrict__ lo, int n4)
{
    int i = blockIdx.x * 256 + threadIdx.x;
    if (i >= n4) return;
    float4 v = ((const float4*)x)[i];
    __half2 h01, h23, l01, l23;
    split4f(v, h01, h23, l01, l23);
    ((__half2*)hi)[2 * i] = h01; ((__half2*)hi)[2 * i + 1] = h23;
    ((__half2*)lo)[2 * i] = l01; ((__half2*)lo)[2 * i + 1] = l23;
}

// Wv1,Wv2 need hi+lo (3-term); writes hi to slots 0,1 and lo to slots 0,1
__global__ void __launch_bounds__(256) split2_kernel(
    const float* __restrict__ p0, const float* __restrict__ p1,
    __half* __restrict__ hi, __half* __restrict__ lo)
{
    int i = blockIdx.x * 256 + threadIdx.x;
    int wsel = i >> 18;
    int j = i & 262143;
    const float* x = (wsel == 0) ? p0 : p1;
    float4 v = ((const float4*)x)[j];
    __half2 h01, h23, l01, l23;
    split4f(v, h01, h23, l01, l23);
    ((__half2*)hi)[2 * i] = h01; ((__half2*)hi)[2 * i + 1] = h23;
    ((__half2*)lo)[2 * i] = l01; ((__half2*)lo)[2 * i + 1] = l23;
}

__global__ void __launch_bounds__(256) conv_hi_kernel(
    const float* __restrict__ x, __half* __restrict__ hi, int n4)
{
    int i = blockIdx.x * 256 + threadIdx.x;
    if (i >= n4) return;
    float4 v = ((const float4*)x)[i];
    ((__half2*)hi)[2 * i]     = __floats2half2_rn(v.x, v.y);
    ((__half2*)hi)[2 * i + 1] = __floats2half2_rn(v.z, v.w);
}

__global__ void __launch_bounds__(256) conv4_hi_kernel(
    const float* __restrict__ p0, const float* __restrict__ p1,
    const float* __restrict__ p2, const float* __restrict__ p3,
    __half* __restrict__ hi)
{
    int i = blockIdx.x * 256 + threadIdx.x;
    int wsel = i >> 18;
    int j = i & 262143;
    const float* x = (wsel == 0) ? p0 : (wsel == 1) ? p1 : (wsel == 2) ? p2 : p3;
    float4 v = ((const float4*)x)[j];
    ((__half2*)hi)[2 * i]     = __floats2half2_rn(v.x, v.y);
    ((__half2*)hi)[2 * i + 1] = __floats2half2_rn(v.z, v.w);
}

// ----------------------------- HMMA GEMM core (128x128 tile) ---------------
static constexpr int T128 = 128 * 80;                 // 10240
static constexpr int STAGE3 = 4 * T128;               // Ah Al Wh Wl
static constexpr int STAGE1 = 2 * T128;               // Ah Wh
static constexpr int SMEM3 = 2 * STAGE3;              // 81920
static constexpr int SMEM1 = 2 * STAGE1;              // 40960

template <int TERMS>
__device__ __forceinline__ void gemm_mainloop128(
    const __half* __restrict__ Ah, const __half* __restrict__ Al,
    const __half* __restrict__ Wh, const __half* __restrict__ Wl,
    uint32_t sb, int bm, int bn, int t, float acc[4][4][4])
{
    constexpr int STAGE = (TERMS == 3) ? STAGE3 : STAGE1;
    constexpr int WOFF  = (TERMS == 3) ? 2 * T128 : T128;
    int lane = t & 31, wid = t >> 5;
    int wm = (wid & 1) * 64;
    int wn = (wid >> 1) * 32;

    int r0 = t >> 2, c0 = t & 3;
    int r1 = (t + 256) >> 2;

    auto stage_load = [&](int s, int k0) {
        uint32_t base = sb + s * STAGE;
        cp_async16(base + r0 * 80 + c0 * 16, Ah + (size_t)(bm + r0) * 1024 + k0 + c0 * 8);
        cp_async16(base + r1 * 80 + c0 * 16, Ah + (size_t)(bm + r1) * 1024 + k0 + c0 * 8);
        if (TERMS == 3) {
            cp_async16(base + T128 + r0 * 80 + c0 * 16,
                       Al + (size_t)(bm + r0) * 1024 + k0 + c0 * 8);
            cp_async16(base + T128 + r1 * 80 + c0 * 16,
                       Al + (size_t)(bm + r1) * 1024 + k0 + c0 * 8);
        }
        uint32_t wb = base + WOFF;
        cp_async16(wb + r0 * 80 + c0 * 16, Wh + (size_t)(bn + r0) * 1024 + k0 + c0 * 8);
        cp_async16(wb + r1 * 80 + c0 * 16, Wh + (size_t)(bn + r1) * 1024 + k0 + c0 * 8);
        if (TERMS == 3) {
            uint32_t wlb = wb + T128;
            cp_async16(wlb + r0 * 80 + c0 * 16, Wl + (size_t)(bn + r0) * 1024 + k0 + c0 * 8);
            cp_async16(wlb + r1 * 80 + c0 * 16, Wl + (size_t)(bn + r1) * 1024 + k0 + c0 * 8);
        }
        cp_commit();
    };

    stage_load(0, 0);

    int a_r = (lane & 15);
    int a_c = (lane >> 4) << 3;
    int b4_r = (lane & 7) + ((lane >> 4) & 1) * 8;
    int b4_c = ((lane >> 3) & 1) << 3;

    for (int c = 0; c < 32; c++) {
        if (c + 1 < 32) {
            stage_load((c + 1) & 1, (c + 1) * 32);
            cp_wait1();
        } else {
            cp_wait0();
        }
        __syncthreads();

        uint32_t base = sb + (c & 1) * STAGE;
        uint32_t tAh = base, tAl = base + T128;
        uint32_t tWh = base + WOFF, tWl = tWh + T128;

#pragma unroll
        for (int kk = 0; kk < 32; kk += 16) {
            uint32_t ah[4][4], al[4][4];
#pragma unroll
            for (int mt = 0; mt < 4; mt++) {
                uint32_t off = (uint32_t)((wm + mt * 16 + a_r) * 80 + (kk + a_c) * 2);
                ldmatrix_x4(ah[mt], tAh + off);
                if (TERMS == 3) ldmatrix_x4(al[mt], tAl + off);
            }
#pragma unroll
            for (int np = 0; np < 2; np++) {
                uint32_t off = (uint32_t)((wn + np * 16 + b4_r) * 80 + (kk + b4_c) * 2);
                uint32_t bh4[4];
                ldmatrix_x4(bh4, tWh + off);
                // term-major: hh first (8 distinct accs)
#pragma unroll
                for (int mt = 0; mt < 4; mt++) {
                    mma_f16(acc[mt][2 * np + 0], ah[mt], bh4 + 0);
                    mma_f16(acc[mt][2 * np + 1], ah[mt], bh4 + 2);
                }
                if (TERMS == 3) {
                    uint32_t bl4[4];
                    ldmatrix_x4(bl4, tWl + off);
#pragma unroll
                    for (int mt = 0; mt < 4; mt++) {
                        mma_f16(acc[mt][2 * np + 0], ah[mt], bl4 + 0);
                        mma_f16(acc[mt][2 * np + 1], ah[mt], bl4 + 2);
                    }
#pragma unroll
                    for (int mt = 0; mt < 4; mt++) {
                        mma_f16(acc[mt][2 * np + 0], al[mt], bh4 + 0);
                        mma_f16(acc[mt][2 * np + 1], al[mt], bh4 + 2);
                    }
                }
            }
        }
        __syncthreads();
    }
}

// epilogues (128-row tile)
__device__ __forceinline__ void epi_head_pair(
    float acc[4][4][4], const float* bias, __half* outh, __half* outl,
    int bm, int bn, int t, int n_per_b)
{
    int lane = t & 31, wid = t >> 5;
    int wm = (wid & 1) * 64, wn = (wid >> 1) * 32;
#pragma unroll
    for (int mt = 0; mt < 4; mt++) {
        int row_a = bm + wm + mt * 16 + (lane >> 2);
#pragma unroll
        for (int rr = 0; rr < 2; rr++) {
            int row = row_a + rr * 8;
            int b = row / n_per_b, ii = row % n_per_b;
#pragma unroll
            for (int nt = 0; nt < 4; nt++) {
                int o = bn + wn + nt * 8 + (lane & 3) * 2;
                float vx = acc[mt][nt][rr * 2 + 0] + bias[o];
                float vy = acc[mt][nt][rr * 2 + 1] + bias[o + 1];
                int h = o >> 6, d = o & 63;
                size_t idx = ((((size_t)(b * 16 + h) * n_per_b + ii) << 6) + (size_t)d) >> 1;
                __half hx = __float2half_rn(vx), hy = __float2half_rn(vy);
                __half lx = __float2half_rn(vx - __half2float(hx));
                __half ly = __float2half_rn(vy - __half2float(hy));
                ((__half2*)outh)[idx] = __half2{hx, hy};
                ((__half2*)outl)[idx] = __half2{lx, ly};
            }
        }
    }
}

__device__ __forceinline__ void epi_head_hi(
    float acc[4][4][4], const float* bias, __half* outh,
    int bm, int bn, int t, int n_per_b)
{
    int lane = t & 31, wid = t >> 5;
    int wm = (wid & 1) * 64, wn = (wid >> 1) * 32;
#pragma unroll
    for (int mt = 0; mt < 4; mt++) {
        int row_a = bm + wm + mt * 16 + (lane >> 2);
#pragma unroll
        for (int rr = 0; rr < 2; rr++) {
            int row = row_a + rr * 8;
            int b = row / n_per_b, ii = row % n_per_b;
#pragma unroll
            for (int nt = 0; nt < 4; nt++) {
                int o = bn + wn + nt * 8 + (lane & 3) * 2;
                float vx = acc[mt][nt][rr * 2 + 0] + bias[o];
                float vy = acc[mt][nt][rr * 2 + 1] + bias[o + 1];
                int h = o >> 6, d = o & 63;
                size_t idx = ((((size_t)(b * 16 + h) * n_per_b + ii) << 6) + (size_t)d) >> 1;
                ((__half2*)outh)[idx] =
                    __half2{__float2half_rn(vx), __float2half_rn(vy)};
            }
        }
    }
}

// batched v-projection: wsel 0=Q(3t) 1=K(3t) 2=V3(1t) 3=V4(1t)
__global__ void __launch_bounds__(256, 2) hmma_gemm_v4(
    const __half* __restrict__ Ah, const __half* __restrict__ Al,
    const __half* __restrict__ WhB, const __half* __restrict__ WlB,
    const float* __restrict__ bv1, const float* __restrict__ bv2,
    const float* __restrict__ bv3, const float* __restrict__ bv4,
    __half* __restrict__ Qh, __half* __restrict__ Ql,
    __half* __restrict__ Kh, __half* __restrict__ Kl,
    __half* __restrict__ V3h, __half* __restrict__ V4h)
{
    extern __shared__ char smem[];
    const uint32_t sb = smem_u32(smem);
    int t = threadIdx.x;
    int wsel = blockIdx.x & 3;
    int bn = (blockIdx.x >> 2) * 128;
    int bm = blockIdx.y * 128;

    float acc[4][4][4];
#pragma unroll
    for (int i = 0; i < 4; i++)
#pragma unroll
        for (int j = 0; j < 4; j++)
#pragma unroll
            for (int k = 0; k < 4; k++) acc[i][j][k] = 0.f;

    const __half* Wh = WhB + (size_t)wsel * 1048576;

    if (wsel < 2) {
        const __half* Wl = WlB + (size_t)wsel * 1048576;
        gemm_mainloop128<3>(Ah, Al, Wh, Wl, sb, bm, bn, t, acc);
        if (wsel == 0) epi_head_pair(acc, bv1, Qh, Ql, bm, bn, t, 1024);
        else           epi_head_pair(acc, bv2, Kh, Kl, bm, bn, t, 1024);
    } else {
        gemm_mainloop128<1>(Ah, nullptr, Wh, nullptr, sb, bm, bn, t, acc);
        if (wsel == 2) epi_head_hi(acc, bv3, V3h, bm, bn, t, 1024);
        else           epi_head_hi(acc, bv4, V4h, bm, bn, t, 1024);
    }
}

__global__ void __launch_bounds__(256, 2) hmma_gemm_w1(
    const __half* __restrict__ Ah, const __half* __restrict__ Wh,
    const float* __restrict__ bias, __half* __restrict__ W1h)
{
    extern __shared__ char smem[];
    const uint32_t sb = smem_u32(smem);
    int t = threadIdx.x;
    int bn = blockIdx.x * 128, bm = blockIdx.y * 128;
    float acc[4][4][4];
#pragma unroll
    for (int i = 0; i < 4; i++)
#pragma unroll
        for (int j = 0; j < 4; j++)
#pragma unroll
            for (int k = 0; k < 4; k++) acc[i][j][k] = 0.f;
    gemm_mainloop128<1>(Ah, nullptr, Wh, nullptr, sb, bm, bn, t, acc);
    epi_head_hi(acc, bias, W1h, bm, bn, t, 128);
}

__global__ void __launch_bounds__(256, 2) hmma_gemm_out(
    const __half* __restrict__ Ah, const __half* __restrict__ Wh,
    const float* __restrict__ bias, float* __restrict__ outf)
{
    extern __shared__ char smem[];
    const uint32_t sb = smem_u32(smem);
    int t = threadIdx.x;
    int bn = blockIdx.x * 128, bm = blockIdx.y * 128;
    float acc[4][4][4];
#pragma unroll
    for (int i = 0; i < 4; i++)
#pragma unroll
        for (int j = 0; j < 4; j++)
#pragma unroll
            for (int k = 0; k < 4; k++) acc[i][j][k] = 0.f;
    gemm_mainloop128<1>(Ah, nullptr, Wh, nullptr, sb, bm, bn, t, acc);

    int lane = t & 31, wid = t >> 5;
    int wm = (wid & 1) * 64, wn = (wid >> 1) * 32;
#pragma unroll
    for (int mt = 0; mt < 4; mt++) {
        int row_a = bm + wm + mt * 16 + (lane >> 2);
#pragma unroll
        for (int rr = 0; rr < 2; rr++) {
            int row = row_a + rr * 8;
#pragma unroll
            for (int nt = 0; nt < 4; nt++) {
                int o = bn + wn + nt * 8 + (lane & 3) * 2;
                float vx = acc[mt][nt][rr * 2 + 0] + bias[o];
                float vy = acc[mt][nt][rr * 2 + 1] + bias[o + 1];
                *(float2*)&outf[(size_t)row * 1024 + o] = float2{vx, vy};
            }
        }
    }
}

// ---------------------------------------------------------------------------
// HMMA cross scores (1-term), one-shot K=64
// ---------------------------------------------------------------------------
static constexpr int XPITCH = 144;
static constexpr int X_T = 128 * XPITCH;
static constexpr int XS_SMEM = 2 * X_T;

__global__ void __launch_bounds__(256) cross_scores_hmma(
    const __half* __restrict__ W1h,
    const __half* __restrict__ V3h, float* __restrict__ S)
{
    extern __shared__ char smem[];
    const uint32_t sb = smem_u32(smem);
    int t = threadIdx.x, lane = t & 31, wid = t >> 5;
    int vt = blockIdx.x, bh = blockIdx.y;

    const __half* a_h = W1h + (size_t)bh * 8192;
    const __half* b_h = V3h + (size_t)bh * 65536 + (size_t)vt * 8192;

#pragma unroll
    for (int it = 0; it < 4; it++) {
        int ch = t + it * 256;
        int row = ch >> 3, cc = ch & 7;
        size_t g = (size_t)row * 64 + cc * 8;
        uint32_t d = (uint32_t)(row * XPITCH + cc * 16);
        cp_async16(sb + 0 * X_T + d, a_h + g);
        cp_async16(sb + 1 * X_T + d, b_h + g);
    }
    cp_commit();
    cp_wait0();
    __syncthreads();

    int wm = (wid & 1) * 64, wn = (wid >> 1) * 32;
    int a_r = lane & 15, a_c = (lane >> 4) << 3;
    int b4_r = (lane & 7) + ((lane >> 4) & 1) * 8;
    int b4_c = ((lane >> 3) & 1) << 3;

    float acc[4][4][4];
#pragma unroll
    for (int i = 0; i < 4; i++)
#pragma unroll
        for (int j = 0; j < 4; j++)
#pragma unroll
            for (int k = 0; k < 4; k++) acc[i][j][k] = 0.f;

#pragma unroll
    for (int ks = 0; ks < 4; ks++) {
        uint32_t ah[4][4];
#pragma unroll
        for (int mt = 0; mt < 4; mt++) {
            uint32_t off = (uint32_t)((wm + mt * 16 + a_r) * XPITCH + (ks * 16 + a_c) * 2);
            ldmatrix_x4(ah[mt], sb + 0 * X_T + off);
        }
#pragma unroll
        for (int np = 0; np < 2; np++) {
            uint32_t off = (uint32_t)((wn + np * 16 + b4_r) * XPITCH + (ks * 16 + b4_c) * 2);
            uint32_t bh4[4];
            ldmatrix_x4(bh4, sb + 1 * X_T + off);
#pragma unroll
            for (int mt = 0; mt < 4; mt++) {
                mma_f16(acc[mt][2 * np + 0], ah[mt], bh4 + 0);
                mma_f16(acc[mt][2 * np + 1], ah[mt], bh4 + 2);
            }
        }
    }

    float* Sb = S + (size_t)bh * 131072;
#pragma unroll
    for (int mt = 0; mt < 4; mt++) {
        int row_a = wm + mt * 16 + (lane >> 2);
#pragma unroll
        for (int rr = 0; rr < 2; rr++) {
            int w = row_a + rr * 8;
#pragma unroll
            for (int nt = 0; nt < 4; nt++) {
                int v = vt * 128 + wn + nt * 8 + (lane & 3) * 2;
                *(float2*)&Sb[(size_t)w * 1024 + v] =
                    float2{acc[mt][nt][rr * 2 + 0], acc[mt][nt][rr * 2 + 1]};
            }
        }
    }
}

// ---------------------------------------------------------------------------
// Fused softmax + column-sum
// ---------------------------------------------------------------------------
__global__ void __launch_bounds__(256) cross_softsum(
    const float* __restrict__ S, float* __restrict__ cross)
{
    int bh = blockIdx.x;
    int t = threadIdx.x, lane = t & 31, w = t >> 5;
    __shared__ float sm[128], siv[128];
    const float* Sb = S + (size_t)bh * 131072;

    for (int r = w; r < 128; r += 8) {
        const float4* p = (const float4*)(Sb + (size_t)r * 1024);
        float mx = -1e30f;
#pragma unroll
        for (int j = 0; j < 8; j++) {
            float4 v = p[lane + j * 32];
            mx = fmaxf(fmaxf(mx, fmaxf(v.x, v.y)), fmaxf(v.z, v.w));
        }
#pragma unroll
        for (int o = 16; o; o >>= 1) mx = fmaxf(mx, __shfl_xor_sync(0xffffffffu, mx, o));
        float sum = 0.f;
#pragma unroll
        for (int j = 0; j < 8; j++) {
            float4 v = p[lane + j * 32];
            sum += __expf(v.x - mx) + __expf(v.y - mx)
                 + __expf(v.z - mx) + __expf(v.w - mx);
        }
#pragma unroll
        for (int o = 16; o; o >>= 1) sum += __shfl_xor_sync(0xffffffffu, sum, o);
        if (lane == 0) { sm[r] = mx; siv[r] = 1.f / sum; }
    }
    __syncthreads();

    float a0 = 0.f, a1 = 0.f, a2 = 0.f, a3 = 0.f;
    int cb = t * 4;
    for (int r = 0; r < 128; r++) {
        float m = sm[r], iv = siv[r];
        float4 v = *(const float4*)(Sb + (size_t)r * 1024 + cb);
        a0 += __expf(v.x - m) * iv;
        a1 += __expf(v.y - m) * iv;
        a2 += __expf(v.z - m) * iv;
        a3 += __expf(v.w - m) * iv;
    }
    *(float4*)(cross + (size_t)bh * 1024 + cb) = float4{a0, a1, a2, a3};
}

// ---------------------------------------------------------------------------
// HMMA flash self-attention: QK 3-term, PV 1-term; x4 LDSM; 2 CTAs/SM.
// ---------------------------------------------------------------------------
static constexpr int APITCH = 144;
static constexpr int AQ_BYTES  = 128 * APITCH;
static constexpr int AKV_T     = 64 * APITCH;
static constexpr int AKV_BUF   = 3 * AKV_T + 256;
static constexpr int AKV_BASE  = 2 * AQ_BYTES;
static constexpr int ATTN_SMEM = AKV_BASE + 2 * AKV_BUF;

__global__ void __launch_bounds__(256, 2) attn_hmma(
    const __half* __restrict__ Qh_g, const __half* __restrict__ Ql_g,
    const __half* __restrict__ Kh_g, const __half* __restrict__ Kl_g,
    const __half* __restrict__ Vh_g,
    const float* __restrict__ cross,
    __half* __restrict__ Ch)
{
    extern __shared__ char smem[];
    const uint32_t sb = smem_u32(smem);
    int t = threadIdx.x;
    int lane = t & 31, w = t >> 5;
    int bh = blockIdx.y, qt = blockIdx.x;
    int b = bh >> 4, h = bh & 15;

    const __half* qh_g = Qh_g + (size_t)bh * 65536 + (size_t)qt * 8192;
    const __half* ql_g = Ql_g + (size_t)bh * 65536 + (size_t)qt * 8192;
    const __half* kh_g = Kh_g + (size_t)bh * 65536;
    const __half* kl_g = Kl_g + (size_t)bh * 65536;
    const __half* vh_g = Vh_g + (size_t)bh * 65536;
    const float* cr = cross + (size_t)bh * 1024;

    {
#pragma unroll
        for (int it = 0; it < 4; it++) {
            int ch = t + it * 256;
            int row = ch >> 3, cc = ch & 7;
            cp_async16(sb + row * APITCH + cc * 16, qh_g + (size_t)row * 64 + cc * 8);
            cp_async16(sb + AQ_BYTES + row * APITCH + cc * 16,
                       ql_g + (size_t)row * 64 + cc * 8);
        }
    }

    auto stage_kv = [&](int s, int kb) {
        uint32_t base = sb + AKV_BASE + s * AKV_BUF;
        int krow0 = kb * 64;
#pragma unroll
        for (int it = 0; it < 2; it++) {
            int ch = t + it * 256;
            int row = ch >> 3, cc = ch & 7;
            size_t g = (size_t)(krow0 + row) * 64 + cc * 8;
            uint32_t d = base + row * APITCH + cc * 16;
            cp_async16(d + 0 * AKV_T, kh_g + g);
            cp_async16(d + 1 * AKV_T, kl_g + g);
            cp_async16(d + 2 * AKV_T, vh_g + g);
        }
        if (t < 16) cp_async16(base + 3 * AKV_T + t * 16, cr + kb * 64 + t * 4);
        cp_commit();
    };

    stage_kv(0, 0);
    cp_wait0();
    __syncthreads();

    uint32_t qh[4][4], ql[4][4];
    {
        int a_r = w * 16 + (lane & 15);
        int a_c = (lane >> 4) << 3;
#pragma unroll
        for (int ks = 0; ks < 4; ks++) {
            uint32_t off = (uint32_t)(a_r * APITCH + (ks * 16 + a_c) * 2);
            ldmatrix_x4(qh[ks], sb + off);
            ldmatrix_x4(ql[ks], sb + AQ_BYTES + off);
        }
    }

    float o[8][4];
#pragma unroll
    for (int i = 0; i < 8; i++)
#pragma unroll
        for (int j = 0; j < 4; j++) o[i][j] = 0.f;
    float m0 = -1e30f, m1 = -1e30f, l0 = 0.f, l1 = 0.f;

    int c2 = (lane & 3) * 2;
    // x4 B addressing (same as GEMM): covers 16 n-rows x k16
    int b4_r = (lane & 7) + ((lane >> 4) & 1) * 8;
    int b4_c = ((lane >> 3) & 1) << 3;
    // x4 trans V addressing: rows k16, two col-tiles
    int v_r4 = (lane & 7) + ((lane >> 3) & 1) * 8;
    int v_csel = (lane >> 4) & 1;

    for (int kb = 0; kb < 16; kb++) {
        if (kb + 1 < 16) stage_kv((kb + 1) & 1, kb + 1);

        uint32_t kvb = sb + AKV_BASE + (kb & 1) * AKV_BUF;
        const float* crs = (const float*)(smem + AKV_BASE + (kb & 1) * AKV_BUF + 3 * AKV_T);

        float s[8][4];
#pragma unroll
        for (int nt = 0; nt < 8; nt++) {
            float b0 = crs[nt * 8 + c2];
            float b1 = crs[nt * 8 + c2 + 1];
            s[nt][0] = b0; s[nt][1] = b1; s[nt][2] = b0; s[nt][3] = b1;
        }

        // QK: nt pairs via single x4 loads
#pragma unroll
        for (int ks = 0; ks < 4; ks++) {
#pragma unroll
            for (int ntp = 0; ntp < 4; ntp++) {
                int nt0 = 2 * ntp, nt1 = nt0 + 1;
                uint32_t off = (uint32_t)((ntp * 16 + b4_r) * APITCH + (ks * 16 + b4_c) * 2);
                uint32_t kh4[4], kl4[4];
                ldmatrix_x4(kh4, kvb + off);
                ldmatrix_x4(kl4, kvb + AKV_T + off);
                mma_f16(s[nt0], qh[ks], kh4 + 0);
                mma_f16(s[nt1], qh[ks], kh4 + 2);
                mma_f16(s[nt0], qh[ks], kl4 + 0);
                mma_f16(s[nt1], qh[ks], kl4 + 2);
                mma_f16(s[nt0], ql[ks], kh4 + 0);
                mma_f16(s[nt1], ql[ks], kh4 + 2);
            }
        }

        float mx0 = -1e30f, mx1 = -1e30f;
#pragma unroll
        for (int nt = 0; nt < 8; nt++) {
            mx0 = fmaxf(mx0, fmaxf(s[nt][0], s[nt][1]));
            mx1 = fmaxf(mx1, fmaxf(s[nt][2], s[nt][3]));
        }
        mx0 = fmaxf(mx0, __shfl_xor_sync(0xffffffffu, mx0, 1));
        mx0 = fmaxf(mx0, __shfl_xor_sync(0xffffffffu, mx0, 2));
        mx1 = fmaxf(mx1, __shfl_xor_sync(0xffffffffu, mx1, 1));
        mx1 = fmaxf(mx1, __shfl_xor_sync(0xffffffffu, mx1, 2));
        float mn0 = fmaxf(m0, mx0), mn1 = fmaxf(m1, mx1);
        float sc0 = __expf(m0 - mn0), sc1 = __expf(m1 - mn1);
        m0 = mn0; m1 = mn1;

        float rs0 = 0.f, rs1 = 0.f;
        uint32_t ph0[8], ph1[8];
#pragma unroll
        for (int nt = 0; nt < 8; nt++) {
            float p0 = __expf(s[nt][0] - mn0);
            float p1 = __expf(s[nt][1] - mn0);
            float p2 = __expf(s[nt][2] - mn1);
            float p3 = __expf(s[nt][3] - mn1);
            rs0 += p0 + p1; rs1 += p2 + p3;
            __half2 hA = __floats2half2_rn(p0, p1);
            __half2 hB = __floats2half2_rn(p2, p3);
            ph0[nt] = *(uint32_t*)&hA;
            ph1[nt] = *(uint32_t*)&hB;
        }
        rs0 += __shfl_xor_sync(0xffffffffu, rs0, 1);
        rs0 += __shfl_xor_sync(0xffffffffu, rs0, 2);
        rs1 += __shfl_xor_sync(0xffffffffu, rs1, 1);
        rs1 += __shfl_xor_sync(0xffffffffu, rs1, 2);
        l0 = l0 * sc0 + rs0;
        l1 = l1 * sc1 + rs1;
#pragma unroll
        for (int nt = 0; nt < 8; nt++) {
            o[nt][0] *= sc0; o[nt][1] *= sc0;
            o[nt][2] *= sc1; o[nt][3] *= sc1;
        }

        // PV: nt pairs via single x4.trans loads
#pragma unroll
        for (int kt = 0; kt < 4; kt++) {
            uint32_t ah[4] = {ph0[2 * kt], ph1[2 * kt], ph0[2 * kt + 1], ph1[2 * kt + 1]};
#pragma unroll
            for (int ntp = 0; ntp < 4; ntp++) {
                int nt0 = 2 * ntp, nt1 = nt0 + 1;
                uint32_t voff = (uint32_t)((kt * 16 + v_r4) * APITCH
                                           + (2 * ntp + v_csel) * 16);
                uint32_t vh4[4];
                ldmatrix_x4_trans(vh4, kvb + 2 * AKV_T + voff);
                mma_f16(o[nt0], ah, vh4 + 0);
                mma_f16(o[nt1], ah, vh4 + 2);
            }
        }

        if (kb + 1 < 16) {
            cp_wait0();
            __syncthreads();
        }
    }

    float inv0 = 1.f / l0, inv1 = 1.f / l1;
    int row0 = qt * 128 + w * 16 + (lane >> 2);
    __half2* Ch2 = (__half2*)Ch;
#pragma unroll
    for (int nt = 0; nt < 8; nt++) {
        int d = nt * 8 + c2;
        {
            float x0 = o[nt][0] * inv0, x1 = o[nt][1] * inv0;
            size_t idx = (((size_t)b * 1024 + row0) * 1024 + h * 64 + d) >> 1;
            Ch2[idx] = __floats2half2_rn(x0, x1);
        }
        {
            float x0 = o[nt][2] * inv1, x1 = o[nt][3] * inv1;
            size_t idx = (((size_t)b * 1024 + row0 + 8) * 1024 + h * 64 + d) >> 1;
            Ch2[idx] = __floats2half2_rn(x0, x1);
        }
    }
}

// ---------------------------------------------------------------------------
// Launch (idx 3 = hmma_gemm_v4 -> ncu profiles it)
// ---------------------------------------------------------------------------
extern "C" void kernel_launch(void* const* d_in, const int* in_sizes, int n_in,
                              void* d_out, int out_size)
{
    const float* w_feat = (const float*)d_in[0];
    const float* v_feat = (const float*)d_in[1];
    const float* Ww1  = (const float*)d_in[2];
    const float* bw1  = (const float*)d_in[3];
    const float* Wv1  = (const float*)d_in[4];
    const float* bv1  = (const float*)d_in[5];
    const float* Wv2  = (const float*)d_in[6];
    const float* bv2  = (const float*)d_in[7];
    const float* Wv3  = (const float*)d_in[8];
    const float* bv3  = (const float*)d_in[9];
    const float* Wv4  = (const float*)d_in[10];
    const float* bv4  = (const float*)d_in[11];
    const float* Wout = (const float*)d_in[12];
    const float* bout = (const float*)d_in[13];
    float* out = (float*)d_out;

    float *Sp, *crp;
    cudaGetSymbolAddress((void**)&Sp,  g_S);
    cudaGetSymbolAddress((void**)&crp, g_cr);

    __half *Qh, *Ql, *Kh, *Kl, *V4h, *V3h, *W1h;
    cudaGetSymbolAddress((void**)&Qh,  g_Qh);
    cudaGetSymbolAddress((void**)&Ql,  g_Ql);
    cudaGetSymbolAddress((void**)&Kh,  g_Kh);
    cudaGetSymbolAddress((void**)&Kl,  g_Kl);
    cudaGetSymbolAddress((void**)&V4h, g_V4h);
    cudaGetSymbolAddress((void**)&V3h, g_V3h);
    cudaGetSymbolAddress((void**)&W1h, g_W1h);

    __half *Ahv, *Alv, *Ahw, *Whp, *Wlp, *Chp;
    cudaGetSymbolAddress((void**)&Ahv, g_Ahv);
    cudaGetSymbolAddress((void**)&Alv, g_Alv);
    cudaGetSymbolAddress((void**)&Ahw, g_Ahw);
    cudaGetSymbolAddress((void**)&Whp, g_Wh);
    cudaGetSymbolAddress((void**)&Wlp, g_Wl);
    cudaGetSymbolAddress((void**)&Chp, g_Ch);

    cudaFuncSetAttribute(hmma_gemm_v4, cudaFuncAttributeMaxDynamicSharedMemorySize, SMEM3);
    cudaFuncSetAttribute(hmma_gemm_w1, cudaFuncAttributeMaxDynamicSharedMemorySize, SMEM1);
    cudaFuncSetAttribute(hmma_gemm_out, cudaFuncAttributeMaxDynamicSharedMemorySize, SMEM1);
    cudaFuncSetAttribute(cross_scores_hmma, cudaFuncAttributeMaxDynamicSharedMemorySize, XS_SMEM);
    cudaFuncSetAttribute(attn_hmma, cudaFuncAttributeMaxDynamicSharedMemorySize, ATTN_SMEM);

    // idx 0..2: inputs for v4
    split_kernel<<<4096, 256>>>(v_feat, Ahv, Alv, 1048576);           // 0
    split2_kernel<<<2048, 256>>>(Wv1, Wv2, Whp, Wlp);                 // 1 (slots 0,1 hi+lo)
    conv4_hi_kernel<<<4096, 256>>>(Wv3, Wv4, Ww1, Wout, Whp + 2ull * 1048576); // 2 (slots 2..5 hi)

    // idx 3: batched v-projections (128x128 tiles)  <-- ncu target
    hmma_gemm_v4<<<dim3(32, 32), 256, SMEM3>>>(
        Ahv, Alv, Whp, Wlp, bv1, bv2, bv3, bv4,
        Qh, Ql, Kh, Kl, V3h, V4h);                                    // 3
    // note: wsel 2 -> Whp slot 2 (Wv3), wsel 3 -> slot 3 (Wv4)

    conv_hi_kernel<<<512, 256>>>(w_feat, Ahw, 131072);                // 4
    hmma_gemm_w1<<<dim3(8, 4), 256, SMEM1>>>(
        Ahw, Whp + 4ull * 1048576, bw1, W1h);                         // 5

    cross_scores_hmma<<<dim3(8, 64), 256, XS_SMEM>>>(W1h, V3h, Sp);   // 6
    cross_softsum<<<64, 256>>>(Sp, crp);                              // 7

    attn_hmma<<<dim3(8, 64), 256, ATTN_SMEM>>>(Qh, Ql, Kh, Kl, V4h, crp, Chp); // 8

    hmma_gemm_out<<<dim3(8, 32), 256, SMEM1>>>(
        Chp, Whp + 5ull * 1048576, bout, out);                        // 9
}

// round 15
// speedup vs baseline: 1.5249x; 1.0521x over previous
#include <cuda_runtime.h>
#include <cuda_fp16.h>
#include <cstdint>
#include <math.h>

// ---------------------------------------------------------------------------
// Shapes: bs=4, H=16, DK=64, D=1024, n_w=128, n_v=1024
// HMMA fp16, calibrated error compensation:
//   3-term: Q/K projections, Q.K^T (score path)
//   1-term: V3/V4/w1 proj, cross, P.V, out proj
// R15: fused conversions; w1 folded into v4 launch (FIXED: all 8 bn tiles).
// ---------------------------------------------------------------------------

__device__ __forceinline__ uint32_t smem_u32(const void* p) {
    uint32_t a;
    asm("{ .reg .u64 t; cvta.to.shared.u64 t, %1; cvt.u32.u64 %0, t; }"
        : "=r"(a) : "l"(p));
    return a;
}

__device__ __forceinline__ void cp_async16(uint32_t dst, const void* src) {
    asm volatile("cp.async.cg.shared.global [%0], [%1], 16;"
                 :: "r"(dst), "l"(src) : "memory");
}
__device__ __forceinline__ void cp_commit() {
    asm volatile("cp.async.commit_group;" ::: "memory");
}
__device__ __forceinline__ void cp_wait0() {
    asm volatile("cp.async.wait_group 0;" ::: "memory");
}
__device__ __forceinline__ void cp_wait1() {
    asm volatile("cp.async.wait_group 1;" ::: "memory");
}

__device__ __forceinline__ void ldmatrix_x4(uint32_t* r, uint32_t addr) {
    asm volatile("ldmatrix.sync.aligned.m8n8.x4.shared.b16 {%0,%1,%2,%3}, [%4];"
                 : "=r"(r[0]), "=r"(r[1]), "=r"(r[2]), "=r"(r[3]) : "r"(addr));
}
__device__ __forceinline__ void ldmatrix_x4_trans(uint32_t* r, uint32_t addr) {
    asm volatile("ldmatrix.sync.aligned.m8n8.x4.trans.shared.b16 {%0,%1,%2,%3}, [%4];"
                 : "=r"(r[0]), "=r"(r[1]), "=r"(r[2]), "=r"(r[3]) : "r"(addr));
}

__device__ __forceinline__ void mma_f16(float* c, const uint32_t* a, const uint32_t* b) {
    asm volatile(
        "mma.sync.aligned.m16n8k16.row.col.f32.f16.f16.f32 "
        "{%0,%1,%2,%3}, {%4,%5,%6,%7}, {%8,%9}, {%0,%1,%2,%3};"
        : "+f"(c[0]), "+f"(c[1]), "+f"(c[2]), "+f"(c[3])
        : "r"(a[0]), "r"(a[1]), "r"(a[2]), "r"(a[3]), "r"(b[0]), "r"(b[1]));
}

// ----------------------------- scratch ------------------------------------
__device__ __align__(256) float g_S [4 * 16 * 128 * 1024];
__device__ __align__(256) float g_cr[4 * 16 * 1024];

__device__ __align__(256) __half g_Qh[4194304], g_Ql[4194304];
__device__ __align__(256) __half g_Kh[4194304], g_Kl[4194304];
__device__ __align__(256) __half g_V4h[4194304];
__device__ __align__(256) __half g_V3h[4194304];
__device__ __align__(256) __half g_W1h[524288];

__device__ __align__(256) __half g_Ahv[4194304], g_Alv[4194304];
__device__ __align__(256) __half g_Ahw[524288];
__device__ __align__(256) __half g_Wh[6 * 1048576], g_Wl[2 * 1048576];
__device__ __align__(256) __half g_Ch[4194304];

// ----------------------------- fused conversions ---------------------------
__global__ void __launch_bounds__(256) convert_all(
    const float* __restrict__ v_feat, const float* __restrict__ w_feat,
    const float* __restrict__ Wv1, const float* __restrict__ Wv2,
    const float* __restrict__ Wv3, const float* __restrict__ Wv4,
    const float* __restrict__ Ww1, const float* __restrict__ Wout,
    __half* __restrict__ Ahv, __half* __restrict__ Alv,
    __half* __restrict__ Whp, __half* __restrict__ Wlp,
    __half* __restrict__ Ahw)
{
    int i = blockIdx.x * 256 + threadIdx.x;
    if (i < 1048576) {
        float4 v = ((const float4*)v_feat)[i];
        __half h0 = __float2half_rn(v.x), h1 = __float2half_rn(v.y);
        __half h2 = __float2half_rn(v.z), h3 = __float2half_rn(v.w);
        ((__half2*)Ahv)[2 * i]     = __half2{h0, h1};
        ((__half2*)Ahv)[2 * i + 1] = __half2{h2, h3};
        ((__half2*)Alv)[2 * i]     = __half2{
            __float2half_rn(v.x - __half2float(h0)),
            __float2half_rn(v.y - __half2float(h1))};
        ((__half2*)Alv)[2 * i + 1] = __half2{
            __float2half_rn(v.z - __half2float(h2)),
            __float2half_rn(v.w - __half2float(h3))};
    } else if (i < 1572864) {
        int j = i - 1048576;
        const float* x = (j >> 18) ? Wv2 : Wv1;
        float4 v = ((const float4*)x)[j & 262143];
        __half h0 = __float2half_rn(v.x), h1 = __float2half_rn(v.y);
        __half h2 = __float2half_rn(v.z), h3 = __float2half_rn(v.w);
        ((__half2*)Whp)[2 * j]     = __half2{h0, h1};
        ((__half2*)Whp)[2 * j + 1] = __half2{h2, h3};
        ((__half2*)Wlp)[2 * j]     = __half2{
            __float2half_rn(v.x - __half2float(h0)),
            __float2half_rn(v.y - __half2float(h1))};
        ((__half2*)Wlp)[2 * j + 1] = __half2{
            __float2half_rn(v.z - __half2float(h2)),
            __float2half_rn(v.w - __half2float(h3))};
    } else if (i < 2621440) {
        int j = i - 1572864;
        int wsel = j >> 18;
        const float* x = (wsel == 0) ? Wv3 : (wsel == 1) ? Wv4
                        : (wsel == 2) ? Ww1 : Wout;
        float4 v = ((const float4*)x)[j & 262143];
        __half2* hp = (__half2*)(Whp + 2ull * 1048576);
        hp[2 * j]     = __floats2half2_rn(v.x, v.y);
        hp[2 * j + 1] = __floats2half2_rn(v.z, v.w);
    } else if (i < 2752512) {
        int j = i - 2621440;
        float4 v = ((const float4*)w_feat)[j];
        ((__half2*)Ahw)[2 * j]     = __floats2half2_rn(v.x, v.y);
        ((__half2*)Ahw)[2 * j + 1] = __floats2half2_rn(v.z, v.w);
    }
}

// ----------------------------- HMMA GEMM core (128x128 tile) ---------------
static constexpr int T128 = 128 * 80;
static constexpr int STAGE3 = 4 * T128;
static constexpr int STAGE1 = 2 * T128;
static constexpr int SMEM3 = 2 * STAGE3;              // 81920
static constexpr int SMEM1 = 2 * STAGE1;              // 40960

template <int TERMS>
__device__ __forceinline__ void gemm_mainloop128(
    const __half* __restrict__ Ah, const __half* __restrict__ Al,
    const __half* __restrict__ Wh, const __half* __restrict__ Wl,
    uint32_t sb, int bm, int bn, int t, float acc[4][4][4])
{
    constexpr int STAGE = (TERMS == 3) ? STAGE3 : STAGE1;
    constexpr int WOFF  = (TERMS == 3) ? 2 * T128 : T128;
    int lane = t & 31, wid = t >> 5;
    int wm = (wid & 1) * 64;
    int wn = (wid >> 1) * 32;

    int r0 = t >> 2, c0 = t & 3;
    int r1 = (t + 256) >> 2;

    auto stage_load = [&](int s, int k0) {
        uint32_t base = sb + s * STAGE;
        cp_async16(base + r0 * 80 + c0 * 16, Ah + (size_t)(bm + r0) * 1024 + k0 + c0 * 8);
        cp_async16(base + r1 * 80 + c0 * 16, Ah + (size_t)(bm + r1) * 1024 + k0 + c0 * 8);
        if (TERMS == 3) {
            cp_async16(base + T128 + r0 * 80 + c0 * 16,
                       Al + (size_t)(bm + r0) * 1024 + k0 + c0 * 8);
            cp_async16(base + T128 + r1 * 80 + c0 * 16,
                       Al + (size_t)(bm + r1) * 1024 + k0 + c0 * 8);
        }
        uint32_t wb = base + WOFF;
        cp_async16(wb + r0 * 80 + c0 * 16, Wh + (size_t)(bn + r0) * 1024 + k0 + c0 * 8);
        cp_async16(wb + r1 * 80 + c0 * 16, Wh + (size_t)(bn + r1) * 1024 + k0 + c0 * 8);
        if (TERMS == 3) {
            uint32_t wlb = wb + T128;
            cp_async16(wlb + r0 * 80 + c0 * 16, Wl + (size_t)(bn + r0) * 1024 + k0 + c0 * 8);
            cp_async16(wlb + r1 * 80 + c0 * 16, Wl + (size_t)(bn + r1) * 1024 + k0 + c0 * 8);
        }
        cp_commit();
    };

    stage_load(0, 0);

    int a_r = (lane & 15);
    int a_c = (lane >> 4) << 3;
    int b4_r = (lane & 7) + ((lane >> 4) & 1) * 8;
    int b4_c = ((lane >> 3) & 1) << 3;

    for (int c = 0; c < 32; c++) {
        if (c + 1 < 32) {
            stage_load((c + 1) & 1, (c + 1) * 32);
            cp_wait1();
        } else {
            cp_wait0();
        }
        __syncthreads();

        uint32_t base = sb + (c & 1) * STAGE;
        uint32_t tAh = base, tAl = base + T128;
        uint32_t tWh = base + WOFF, tWl = tWh + T128;

#pragma unroll
        for (int kk = 0; kk < 32; kk += 16) {
            uint32_t ah[4][4], al[4][4];
#pragma unroll
            for (int mt = 0; mt < 4; mt++) {
                uint32_t off = (uint32_t)((wm + mt * 16 + a_r) * 80 + (kk + a_c) * 2);
                ldmatrix_x4(ah[mt], tAh + off);
                if (TERMS == 3) ldmatrix_x4(al[mt], tAl + off);
            }
#pragma unroll
            for (int np = 0; np < 2; np++) {
                uint32_t off = (uint32_t)((wn + np * 16 + b4_r) * 80 + (kk + b4_c) * 2);
                uint32_t bh4[4];
                ldmatrix_x4(bh4, tWh + off);
#pragma unroll
                for (int mt = 0; mt < 4; mt++) {
                    mma_f16(acc[mt][2 * np + 0], ah[mt], bh4 + 0);
                    mma_f16(acc[mt][2 * np + 1], ah[mt], bh4 + 2);
                }
                if (TERMS == 3) {
                    uint32_t bl4[4];
                    ldmatrix_x4(bl4, tWl + off);
#pragma unroll
                    for (int mt = 0; mt < 4; mt++) {
                        mma_f16(acc[mt][2 * np + 0], ah[mt], bl4 + 0);
                        mma_f16(acc[mt][2 * np + 1], ah[mt], bl4 + 2);
                    }
#pragma unroll
                    for (int mt = 0; mt < 4; mt++) {
                        mma_f16(acc[mt][2 * np + 0], al[mt], bh4 + 0);
                        mma_f16(acc[mt][2 * np + 1], al[mt], bh4 + 2);
                    }
                }
            }
        }
        __syncthreads();
    }
}

// epilogues (128-row tile)
__device__ __forceinline__ void epi_head_pair(
    float acc[4][4][4], const float* bias, __half* outh, __half* outl,
    int bm, int bn, int t, int n_per_b)
{
    int lane = t & 31, wid = t >> 5;
    int wm = (wid & 1) * 64, wn = (wid >> 1) * 32;
#pragma unroll
    for (int mt = 0; mt < 4; mt++) {
        int row_a = bm + wm + mt * 16 + (lane >> 2);
#pragma unroll
        for (int rr = 0; rr < 2; rr++) {
            int row = row_a + rr * 8;
            int b = row / n_per_b, ii = row % n_per_b;
#pragma unroll
            for (int nt = 0; nt < 4; nt++) {
                int o = bn + wn + nt * 8 + (lane & 3) * 2;
                float vx = acc[mt][nt][rr * 2 + 0] + bias[o];
                float vy = acc[mt][nt][rr * 2 + 1] + bias[o + 1];
                int h = o >> 6, d = o & 63;
                size_t idx = ((((size_t)(b * 16 + h) * n_per_b + ii) << 6) + (size_t)d) >> 1;
                __half hx = __float2half_rn(vx), hy = __float2half_rn(vy);
                __half lx = __float2half_rn(vx - __half2float(hx));
                __half ly = __float2half_rn(vy - __half2float(hy));
                ((__half2*)outh)[idx] = __half2{hx, hy};
                ((__half2*)outl)[idx] = __half2{lx, ly};
            }
        }
    }
}

__device__ __forceinline__ void epi_head_hi(
    float acc[4][4][4], const float* bias, __half* outh,
    int bm, int bn, int t, int n_per_b)
{
    int lane = t & 31, wid = t >> 5;
    int wm = (wid & 1) * 64, wn = (wid >> 1) * 32;
#pragma unroll
    for (int mt = 0; mt < 4; mt++) {
        int row_a = bm + wm + mt * 16 + (lane >> 2);
#pragma unroll
        for (int rr = 0; rr < 2; rr++) {
            int row = row_a + rr * 8;
            int b = row / n_per_b, ii = row % n_per_b;
#pragma unroll
            for (int nt = 0; nt < 4; nt++) {
                int o = bn + wn + nt * 8 + (lane & 3) * 2;
                float vx = acc[mt][nt][rr * 2 + 0] + bias[o];
                float vy = acc[mt][nt][rr * 2 + 1] + bias[o + 1];
                int h = o >> 6, d = o & 63;
                size_t idx = ((((size_t)(b * 16 + h) * n_per_b + ii) << 6) + (size_t)d) >> 1;
                ((__half2*)outh)[idx] =
                    __half2{__float2half_rn(vx), __float2half_rn(vy)};
            }
        }
    }
}

// batched projections: grid (40, 32)
//   x<32:  wsel = x&3: 0=Q(3t) 1=K(3t) 2=V3(1t) 3=V4(1t), bn=(x>>2)*128
//   x>=32: w1 projection (1t), bn=(x-32)*128, valid for y<4
__global__ void __launch_bounds__(256, 2) hmma_gemm_v4(
    const __half* __restrict__ Ah, const __half* __restrict__ Al,
    const __half* __restrict__ WhB, const __half* __restrict__ WlB,
    const __half* __restrict__ Ahw,
    const float* __restrict__ bv1, const float* __restrict__ bv2,
    const float* __restrict__ bv3, const float* __restrict__ bv4,
    const float* __restrict__ bw1,
    __half* __restrict__ Qh, __half* __restrict__ Ql,
    __half* __restrict__ Kh, __half* __restrict__ Kl,
    __half* __restrict__ V3h, __half* __restrict__ V4h,
    __half* __restrict__ W1h)
{
    extern __shared__ char smem[];
    const uint32_t sb = smem_u32(smem);
    int t = threadIdx.x;

    float acc[4][4][4];
#pragma unroll
    for (int i = 0; i < 4; i++)
#pragma unroll
        for (int j = 0; j < 4; j++)
#pragma unroll
            for (int k = 0; k < 4; k++) acc[i][j][k] = 0.f;

    if (blockIdx.x >= 32) {
        if (blockIdx.y >= 4) return;
        int bn = (blockIdx.x - 32) * 128;   // 8 bn tiles: full N=1024
        int bm = blockIdx.y * 128;          // 4 bm tiles: full M=512
        gemm_mainloop128<1>(Ahw, nullptr, WhB + 4ull * 1048576, nullptr,
                            sb, bm, bn, t, acc);
        epi_head_hi(acc, bw1, W1h, bm, bn, t, 128);
        return;
    }

    int wsel = blockIdx.x & 3;
    int bn = (blockIdx.x >> 2) * 128;
    int bm = blockIdx.y * 128;
    const __half* Wh = WhB + (size_t)wsel * 1048576;

    if (wsel < 2) {
        const __half* Wl = WlB + (size_t)wsel * 1048576;
        gemm_mainloop128<3>(Ah, Al, Wh, Wl, sb, bm, bn, t, acc);
        if (wsel == 0) epi_head_pair(acc, bv1, Qh, Ql, bm, bn, t, 1024);
        else           epi_head_pair(acc, bv2, Kh, Kl, bm, bn, t, 1024);
    } else {
        gemm_mainloop128<1>(Ah, nullptr, Wh, nullptr, sb, bm, bn, t, acc);
        if (wsel == 2) epi_head_hi(acc, bv3, V3h, bm, bn, t, 1024);
        else           epi_head_hi(acc, bv4, V4h, bm, bn, t, 1024);
    }
}

__global__ void __launch_bounds__(256, 2) hmma_gemm_out(
    const __half* __restrict__ Ah, const __half* __restrict__ Wh,
    const float* __restrict__ bias, float* __restrict__ outf)
{
    extern __shared__ char smem[];
    const uint32_t sb = smem_u32(smem);
    int t = threadIdx.x;
    int bn = blockIdx.x * 128, bm = blockIdx.y * 128;
    float acc[4][4][4];
#pragma unroll
    for (int i = 0; i < 4; i++)
#pragma unroll
        for (int j = 0; j < 4; j++)
#pragma unroll
            for (int k = 0; k < 4; k++) acc[i][j][k] = 0.f;
    gemm_mainloop128<1>(Ah, nullptr, Wh, nullptr, sb, bm, bn, t, acc);

    int lane = t & 31, wid = t >> 5;
    int wm = (wid & 1) * 64, wn = (wid >> 1) * 32;
#pragma unroll
    for (int mt = 0; mt < 4; mt++) {
        int row_a = bm + wm + mt * 16 + (lane >> 2);
#pragma unroll
        for (int rr = 0; rr < 2; rr++) {
            int row = row_a + rr * 8;
#pragma unroll
            for (int nt = 0; nt < 4; nt++) {
                int o = bn + wn + nt * 8 + (lane & 3) * 2;
                float vx = acc[mt][nt][rr * 2 + 0] + bias[o];
                float vy = acc[mt][nt][rr * 2 + 1] + bias[o + 1];
                *(float2*)&outf[(size_t)row * 1024 + o] = float2{vx, vy};
            }
        }
    }
}

// ---------------------------------------------------------------------------
// HMMA cross scores (1-term), one-shot K=64
// ---------------------------------------------------------------------------
static constexpr int XPITCH = 144;
static constexpr int X_T = 128 * XPITCH;
static constexpr int XS_SMEM = 2 * X_T;

__global__ void __launch_bounds__(256) cross_scores_hmma(
    const __half* __restrict__ W1h,
    const __half* __restrict__ V3h, float* __restrict__ S)
{
    extern __shared__ char smem[];
    const uint32_t sb = smem_u32(smem);
    int t = threadIdx.x, lane = t & 31, wid = t >> 5;
    int vt = blockIdx.x, bh = blockIdx.y;

    const __half* a_h = W1h + (size_t)bh * 8192;
    const __half* b_h = V3h + (size_t)bh * 65536 + (size_t)vt * 8192;

#pragma unroll
    for (int it = 0; it < 4; it++) {
        int ch = t + it * 256;
        int row = ch >> 3, cc = ch & 7;
        size_t g = (size_t)row * 64 + cc * 8;
        uint32_t d = (uint32_t)(row * XPITCH + cc * 16);
        cp_async16(sb + 0 * X_T + d, a_h + g);
        cp_async16(sb + 1 * X_T + d, b_h + g);
    }
    cp_commit();
    cp_wait0();
    __syncthreads();

    int wm = (wid & 1) * 64, wn = (wid >> 1) * 32;
    int a_r = lane & 15, a_c = (lane >> 4) << 3;
    int b4_r = (lane & 7) + ((lane >> 4) & 1) * 8;
    int b4_c = ((lane >> 3) & 1) << 3;

    float acc[4][4][4];
#pragma unroll
    for (int i = 0; i < 4; i++)
#pragma unroll
        for (int j = 0; j < 4; j++)
#pragma unroll
            for (int k = 0; k < 4; k++) acc[i][j][k] = 0.f;

#pragma unroll
    for (int ks = 0; ks < 4; ks++) {
        uint32_t ah[4][4];
#pragma unroll
        for (int mt = 0; mt < 4; mt++) {
            uint32_t off = (uint32_t)((wm + mt * 16 + a_r) * XPITCH + (ks * 16 + a_c) * 2);
            ldmatrix_x4(ah[mt], sb + 0 * X_T + off);
        }
#pragma unroll
        for (int np = 0; np < 2; np++) {
            uint32_t off = (uint32_t)((wn + np * 16 + b4_r) * XPITCH + (ks * 16 + b4_c) * 2);
            uint32_t bh4[4];
            ldmatrix_x4(bh4, sb + 1 * X_T + off);
#pragma unroll
            for (int mt = 0; mt < 4; mt++) {
                mma_f16(acc[mt][2 * np + 0], ah[mt], bh4 + 0);
                mma_f16(acc[mt][2 * np + 1], ah[mt], bh4 + 2);
            }
        }
    }

    float* Sb = S + (size_t)bh * 131072;
#pragma unroll
    for (int mt = 0; mt < 4; mt++) {
        int row_a = wm + mt * 16 + (lane >> 2);
#pragma unroll
        for (int rr = 0; rr < 2; rr++) {
            int w = row_a + rr * 8;
#pragma unroll
            for (int nt = 0; nt < 4; nt++) {
                int v = vt * 128 + wn + nt * 8 + (lane & 3) * 2;
                *(float2*)&Sb[(size_t)w * 1024 + v] =
                    float2{acc[mt][nt][rr * 2 + 0], acc[mt][nt][rr * 2 + 1]};
            }
        }
    }
}

// ---------------------------------------------------------------------------
// Fused softmax + column-sum
// ---------------------------------------------------------------------------
__global__ void __launch_bounds__(256) cross_softsum(
    const float* __restrict__ S, float* __restrict__ cross)
{
    int bh = blockIdx.x;
    int t = threadIdx.x, lane = t & 31, w = t >> 5;
    __shared__ float sm[128], siv[128];
    const float* Sb = S + (size_t)bh * 131072;

    for (int r = w; r < 128; r += 8) {
        const float4* p = (const float4*)(Sb + (size_t)r * 1024);
        float mx = -1e30f;
#pragma unroll
        for (int j = 0; j < 8; j++) {
            float4 v = p[lane + j * 32];
            mx = fmaxf(fmaxf(mx, fmaxf(v.x, v.y)), fmaxf(v.z, v.w));
        }
#pragma unroll
        for (int o = 16; o; o >>= 1) mx = fmaxf(mx, __shfl_xor_sync(0xffffffffu, mx, o));
        float sum = 0.f;
#pragma unroll
        for (int j = 0; j < 8; j++) {
            float4 v = p[lane + j * 32];
            sum += __expf(v.x - mx) + __expf(v.y - mx)
                 + __expf(v.z - mx) + __expf(v.w - mx);
        }
#pragma unroll
        for (int o = 16; o; o >>= 1) sum += __shfl_xor_sync(0xffffffffu, sum, o);
        if (lane == 0) { sm[r] = mx; siv[r] = 1.f / sum; }
    }
    __syncthreads();

    float a0 = 0.f, a1 = 0.f, a2 = 0.f, a3 = 0.f;
    int cb = t * 4;
    for (int r = 0; r < 128; r++) {
        float m = sm[r], iv = siv[r];
        float4 v = *(const float4*)(Sb + (size_t)r * 1024 + cb);
        a0 += __expf(v.x - m) * iv;
        a1 += __expf(v.y - m) * iv;
        a2 += __expf(v.z - m) * iv;
        a3 += __expf(v.w - m) * iv;
    }
    *(float4*)(cross + (size_t)bh * 1024 + cb) = float4{a0, a1, a2, a3};
}

// ---------------------------------------------------------------------------
// HMMA flash self-attention: QK 3-term, PV 1-term; x4 LDSM; 2 CTAs/SM.
// ---------------------------------------------------------------------------
static constexpr int APITCH = 144;
static constexpr int AQ_BYTES  = 128 * APITCH;
static constexpr int AKV_T     = 64 * APITCH;
static constexpr int AKV_BUF   = 3 * AKV_T + 256;
static constexpr int AKV_BASE  = 2 * AQ_BYTES;
static constexpr int ATTN_SMEM = AKV_BASE + 2 * AKV_BUF;

__global__ void __launch_bounds__(256, 2) attn_hmma(
    const __half* __restrict__ Qh_g, const __half* __restrict__ Ql_g,
    const __half* __restrict__ Kh_g, const __half* __restrict__ Kl_g,
    const __half* __restrict__ Vh_g,
    const float* __restrict__ cross,
    __half* __restrict__ Ch)
{
    extern __shared__ char smem[];
    const uint32_t sb = smem_u32(smem);
    int t = threadIdx.x;
    int lane = t & 31, w = t >> 5;
    int bh = blockIdx.y, qt = blockIdx.x;
    int b = bh >> 4, h = bh & 15;

    const __half* qh_g = Qh_g + (size_t)bh * 65536 + (size_t)qt * 8192;
    const __half* ql_g = Ql_g + (size_t)bh * 65536 + (size_t)qt * 8192;
    const __half* kh_g = Kh_g + (size_t)bh * 65536;
    const __half* kl_g = Kl_g + (size_t)bh * 65536;
    const __half* vh_g = Vh_g + (size_t)bh * 65536;
    const float* cr = cross + (size_t)bh * 1024;

    {
#pragma unroll
        for (int it = 0; it < 4; it++) {
            int ch = t + it * 256;
            int row = ch >> 3, cc = ch & 7;
            cp_async16(sb + row * APITCH + cc * 16, qh_g + (size_t)row * 64 + cc * 8);
            cp_async16(sb + AQ_BYTES + row * APITCH + cc * 16,
                       ql_g + (size_t)row * 64 + cc * 8);
        }
    }

    auto stage_kv = [&](int s, int kb) {
        uint32_t base = sb + AKV_BASE + s * AKV_BUF;
        int krow0 = kb * 64;
#pragma unroll
        for (int it = 0; it < 2; it++) {
            int ch = t + it * 256;
            int row = ch >> 3, cc = ch & 7;
            size_t g = (size_t)(krow0 + row) * 64 + cc * 8;
            uint32_t d = base + row * APITCH + cc * 16;
            cp_async16(d + 0 * AKV_T, kh_g + g);
            cp_async16(d + 1 * AKV_T, kl_g + g);
            cp_async16(d + 2 * AKV_T, vh_g + g);
        }
        if (t < 16) cp_async16(base + 3 * AKV_T + t * 16, cr + kb * 64 + t * 4);
        cp_commit();
    };

    stage_kv(0, 0);
    cp_wait0();
    __syncthreads();

    uint32_t qh[4][4], ql[4][4];
    {
        int a_r = w * 16 + (lane & 15);
        int a_c = (lane >> 4) << 3;
#pragma unroll
        for (int ks = 0; ks < 4; ks++) {
            uint32_t off = (uint32_t)(a_r * APITCH + (ks * 16 + a_c) * 2);
            ldmatrix_x4(qh[ks], sb + off);
            ldmatrix_x4(ql[ks], sb + AQ_BYTES + off);
        }
    }

    float o[8][4];
#pragma unroll
    for (int i = 0; i < 8; i++)
#pragma unroll
        for (int j = 0; j < 4; j++) o[i][j] = 0.f;
    float m0 = -1e30f, m1 = -1e30f, l0 = 0.f, l1 = 0.f;

    int c2 = (lane & 3) * 2;
    int b4_r = (lane & 7) + ((lane >> 4) & 1) * 8;
    int b4_c = ((lane >> 3) & 1) << 3;
    int v_r4 = (lane & 7) + ((lane >> 3) & 1) * 8;
    int v_csel = (lane >> 4) & 1;

    for (int kb = 0; kb < 16; kb++) {
        if (kb + 1 < 16) stage_kv((kb + 1) & 1, kb + 1);

        uint32_t kvb = sb + AKV_BASE + (kb & 1) * AKV_BUF;
        const float* crs = (const float*)(smem + AKV_BASE + (kb & 1) * AKV_BUF + 3 * AKV_T);

        float s[8][4];
#pragma unroll
        for (int nt = 0; nt < 8; nt++) {
            float b0 = crs[nt * 8 + c2];
            float b1 = crs[nt * 8 + c2 + 1];
            s[nt][0] = b0; s[nt][1] = b1; s[nt][2] = b0; s[nt][3] = b1;
        }

#pragma unroll
        for (int ks = 0; ks < 4; ks++) {
#pragma unroll
            for (int ntp = 0; ntp < 4; ntp++) {
                int nt0 = 2 * ntp, nt1 = nt0 + 1;
                uint32_t off = (uint32_t)((ntp * 16 + b4_r) * APITCH + (ks * 16 + b4_c) * 2);
                uint32_t kh4[4], kl4[4];
                ldmatrix_x4(kh4, kvb + off);
                ldmatrix_x4(kl4, kvb + AKV_T + off);
                mma_f16(s[nt0], qh[ks], kh4 + 0);
                mma_f16(s[nt1], qh[ks], kh4 + 2);
                mma_f16(s[nt0], qh[ks], kl4 + 0);
                mma_f16(s[nt1], qh[ks], kl4 + 2);
                mma_f16(s[nt0], ql[ks], kh4 + 0);
                mma_f16(s[nt1], ql[ks], kh4 + 2);
            }
        }

        float mx0 = -1e30f, mx1 = -1e30f;
#pragma unroll
        for (int nt = 0; nt < 8; nt++) {
            mx0 = fmaxf(mx0, fmaxf(s[nt][0], s[nt][1]));
            mx1 = fmaxf(mx1, fmaxf(s[nt][2], s[nt][3]));
        }
        mx0 = fmaxf(mx0, __shfl_xor_sync(0xffffffffu, mx0, 1));
        mx0 = fmaxf(mx0, __shfl_xor_sync(0xffffffffu, mx0, 2));
        mx1 = fmaxf(mx1, __shfl_xor_sync(0xffffffffu, mx1, 1));
        mx1 = fmaxf(mx1, __shfl_xor_sync(0xffffffffu, mx1, 2));
        float mn0 = fmaxf(m0, mx0), mn1 = fmaxf(m1, mx1);
        float sc0 = __expf(m0 - mn0), sc1 = __expf(m1 - mn1);
        m0 = mn0; m1 = mn1;

        float rs0 = 0.f, rs1 = 0.f;
        uint32_t ph0[8], ph1[8];
#pragma unroll
        for (int nt = 0; nt < 8; nt++) {
            float p0 = __expf(s[nt][0] - mn0);
            float p1 = __expf(s[nt][1] - mn0);
            float p2 = __expf(s[nt][2] - mn1);
            float p3 = __expf(s[nt][3] - mn1);
            rs0 += p0 + p1; rs1 += p2 + p3;
            __half2 hA = __floats2half2_rn(p0, p1);
            __half2 hB = __floats2half2_rn(p2, p3);
            ph0[nt] = *(uint32_t*)&hA;
            ph1[nt] = *(uint32_t*)&hB;
        }
        rs0 += __shfl_xor_sync(0xffffffffu, rs0, 1);
        rs0 += __shfl_xor_sync(0xffffffffu, rs0, 2);
        rs1 += __shfl_xor_sync(0xffffffffu, rs1, 1);
        rs1 += __shfl_xor_sync(0xffffffffu, rs1, 2);
        l0 = l0 * sc0 + rs0;
        l1 = l1 * sc1 + rs1;
#pragma unroll
        for (int nt = 0; nt < 8; nt++) {
            o[nt][0] *= sc0; o[nt][1] *= sc0;
            o[nt][2] *= sc1; o[nt][3] *= sc1;
        }

#pragma unroll
        for (int kt = 0; kt < 4; kt++) {
            uint32_t ah[4] = {ph0[2 * kt], ph1[2 * kt], ph0[2 * kt + 1], ph1[2 * kt + 1]};
#pragma unroll
            for (int ntp = 0; ntp < 4; ntp++) {
                int nt0 = 2 * ntp, nt1 = nt0 + 1;
                uint32_t voff = (uint32_t)((kt * 16 + v_r4) * APITCH
                                           + (2 * ntp + v_csel) * 16);
                uint32_t vh4[4];
                ldmatrix_x4_trans(vh4, kvb + 2 * AKV_T + voff);
                mma_f16(o[nt0], ah, vh4 + 0);
                mma_f16(o[nt1], ah, vh4 + 2);
            }
        }

        if (kb + 1 < 16) {
            cp_wait0();
            __syncthreads();
        }
    }

    float inv0 = 1.f / l0, inv1 = 1.f / l1;
    int row0 = qt * 128 + w * 16 + (lane >> 2);
    __half2* Ch2 = (__half2*)Ch;
#pragma unroll
    for (int nt = 0; nt < 8; nt++) {
        int d = nt * 8 + c2;
        {
            float x0 = o[nt][0] * inv0, x1 = o[nt][1] * inv0;
            size_t idx = (((size_t)b * 1024 + row0) * 1024 + h * 64 + d) >> 1;
            Ch2[idx] = __floats2half2_rn(x0, x1);
        }
        {
            float x0 = o[nt][2] * inv1, x1 = o[nt][3] * inv1;
            size_t idx = (((size_t)b * 1024 + row0 + 8) * 1024 + h * 64 + d) >> 1;
            Ch2[idx] = __floats2half2_rn(x0, x1);
        }
    }
}

// ---------------------------------------------------------------------------
// Launch
// ---------------------------------------------------------------------------
extern "C" void kernel_launch(void* const* d_in, const int* in_sizes, int n_in,
                              void* d_out, int out_size)
{
    const float* w_feat = (const float*)d_in[0];
    const float* v_feat = (const float*)d_in[1];
    const float* Ww1  = (const float*)d_in[2];
    const float* bw1  = (const float*)d_in[3];
    const float* Wv1  = (const float*)d_in[4];
    const float* bv1  = (const float*)d_in[5];
    const float* Wv2  = (const float*)d_in[6];
    const float* bv2  = (const float*)d_in[7];
    const float* Wv3  = (const float*)d_in[8];
    const float* bv3  = (const float*)d_in[9];
    const float* Wv4  = (const float*)d_in[10];
    const float* bv4  = (const float*)d_in[11];
    const float* Wout = (const float*)d_in[12];
    const float* bout = (const float*)d_in[13];
    float* out = (float*)d_out;

    float *Sp, *crp;
    cudaGetSymbolAddress((void**)&Sp,  g_S);
    cudaGetSymbolAddress((void**)&crp, g_cr);

    __half *Qh, *Ql, *Kh, *Kl, *V4h, *V3h, *W1h;
    cudaGetSymbolAddress((void**)&Qh,  g_Qh);
    cudaGetSymbolAddress((void**)&Ql,  g_Ql);
    cudaGetSymbolAddress((void**)&Kh,  g_Kh);
    cudaGetSymbolAddress((void**)&Kl,  g_Kl);
    cudaGetSymbolAddress((void**)&V4h, g_V4h);
    cudaGetSymbolAddress((void**)&V3h, g_V3h);
    cudaGetSymbolAddress((void**)&W1h, g_W1h);

    __half *Ahv, *Alv, *Ahw, *Whp, *Wlp, *Chp;
    cudaGetSymbolAddress((void**)&Ahv, g_Ahv);
    cudaGetSymbolAddress((void**)&Alv, g_Alv);
    cudaGetSymbolAddress((void**)&Ahw, g_Ahw);
    cudaGetSymbolAddress((void**)&Whp, g_Wh);
    cudaGetSymbolAddress((void**)&Wlp, g_Wl);
    cudaGetSymbolAddress((void**)&Chp, g_Ch);

    cudaFuncSetAttribute(hmma_gemm_v4, cudaFuncAttributeMaxDynamicSharedMemorySize, SMEM3);
    cudaFuncSetAttribute(hmma_gemm_out, cudaFuncAttributeMaxDynamicSharedMemorySize, SMEM1);
    cudaFuncSetAttribute(cross_scores_hmma, cudaFuncAttributeMaxDynamicSharedMemorySize, XS_SMEM);
    cudaFuncSetAttribute(attn_hmma, cudaFuncAttributeMaxDynamicSharedMemorySize, ATTN_SMEM);

    // 0: all fp32->fp16 conversions in one launch
    convert_all<<<10752, 256>>>(v_feat, w_feat, Wv1, Wv2, Wv3, Wv4, Ww1, Wout,
                                Ahv, Alv, Whp, Wlp, Ahw);

    // 1: Q/K (3t) + V3/V4 (1t) + w1 (1t, all 8 bn tiles) projections
    hmma_gemm_v4<<<dim3(40, 32), 256, SMEM3>>>(
        Ahv, Alv, Whp, Wlp, Ahw, bv1, bv2, bv3, bv4, bw1,
        Qh, Ql, Kh, Kl, V3h, V4h, W1h);

    // 2..3: cross-attention bias path
    cross_scores_hmma<<<dim3(8, 64), 256, XS_SMEM>>>(W1h, V3h, Sp);
    cross_softsum<<<64, 256>>>(Sp, crp);

    // 4: flash self-attention
    attn_hmma<<<dim3(8, 64), 256, ATTN_SMEM>>>(Qh, Ql, Kh, Kl, V4h, crp, Chp);

    // 5: output projection
    hmma_gemm_out<<<dim3(8, 32), 256, SMEM1>>>(
        Chp, Whp + 5ull * 1048576, bout, out);
}

// round 16
// speedup vs baseline: 1.5348x; 1.0065x over previous
#include <cuda_runtime.h>
#include <cuda_fp16.h>
#include <cstdint>
#include <math.h>

// ---------------------------------------------------------------------------
// Shapes: bs=4, H=16, DK=64, D=1024, n_w=128, n_v=1024
// HMMA fp16, calibrated error compensation:
//   3-term: Q/K projections, Q.K^T (score path)
//   1-term: V3/V4/w1 proj, cross, P.V, out proj
// R16: cross softmax+colsum split into two wide launches (512 / 256 CTAs).
// ---------------------------------------------------------------------------

__device__ __forceinline__ uint32_t smem_u32(const void* p) {
    uint32_t a;
    asm("{ .reg .u64 t; cvta.to.shared.u64 t, %1; cvt.u32.u64 %0, t; }"
        : "=r"(a) : "l"(p));
    return a;
}

__device__ __forceinline__ void cp_async16(uint32_t dst, const void* src) {
    asm volatile("cp.async.cg.shared.global [%0], [%1], 16;"
                 :: "r"(dst), "l"(src) : "memory");
}
__device__ __forceinline__ void cp_commit() {
    asm volatile("cp.async.commit_group;" ::: "memory");
}
__device__ __forceinline__ void cp_wait0() {
    asm volatile("cp.async.wait_group 0;" ::: "memory");
}
__device__ __forceinline__ void cp_wait1() {
    asm volatile("cp.async.wait_group 1;" ::: "memory");
}

__device__ __forceinline__ void ldmatrix_x4(uint32_t* r, uint32_t addr) {
    asm volatile("ldmatrix.sync.aligned.m8n8.x4.shared.b16 {%0,%1,%2,%3}, [%4];"
                 : "=r"(r[0]), "=r"(r[1]), "=r"(r[2]), "=r"(r[3]) : "r"(addr));
}
__device__ __forceinline__ void ldmatrix_x4_trans(uint32_t* r, uint32_t addr) {
    asm volatile("ldmatrix.sync.aligned.m8n8.x4.trans.shared.b16 {%0,%1,%2,%3}, [%4];"
                 : "=r"(r[0]), "=r"(r[1]), "=r"(r[2]), "=r"(r[3]) : "r"(addr));
}

__device__ __forceinline__ void mma_f16(float* c, const uint32_t* a, const uint32_t* b) {
    asm volatile(
        "mma.sync.aligned.m16n8k16.row.col.f32.f16.f16.f32 "
        "{%0,%1,%2,%3}, {%4,%5,%6,%7}, {%8,%9}, {%0,%1,%2,%3};"
        : "+f"(c[0]), "+f"(c[1]), "+f"(c[2]), "+f"(c[3])
        : "r"(a[0]), "r"(a[1]), "r"(a[2]), "r"(a[3]), "r"(b[0]), "r"(b[1]));
}

// ----------------------------- scratch ------------------------------------
__device__ __align__(256) float g_S [4 * 16 * 128 * 1024];
__device__ __align__(256) float g_cr[4 * 16 * 1024];
__device__ __align__(256) float g_sm[8192], g_siv[8192];

__device__ __align__(256) __half g_Qh[4194304], g_Ql[4194304];
__device__ __align__(256) __half g_Kh[4194304], g_Kl[4194304];
__device__ __align__(256) __half g_V4h[4194304];
__device__ __align__(256) __half g_V3h[4194304];
__device__ __align__(256) __half g_W1h[524288];

__device__ __align__(256) __half g_Ahv[4194304], g_Alv[4194304];
__device__ __align__(256) __half g_Ahw[524288];
__device__ __align__(256) __half g_Wh[6 * 1048576], g_Wl[2 * 1048576];
__device__ __align__(256) __half g_Ch[4194304];

// ----------------------------- fused conversions ---------------------------
__global__ void __launch_bounds__(256) convert_all(
    const float* __restrict__ v_feat, const float* __restrict__ w_feat,
    const float* __restrict__ Wv1, const float* __restrict__ Wv2,
    const float* __restrict__ Wv3, const float* __restrict__ Wv4,
    const float* __restrict__ Ww1, const float* __restrict__ Wout,
    __half* __restrict__ Ahv, __half* __restrict__ Alv,
    __half* __restrict__ Whp, __half* __restrict__ Wlp,
    __half* __restrict__ Ahw)
{
    int i = blockIdx.x * 256 + threadIdx.x;
    if (i < 1048576) {
        float4 v = ((const float4*)v_feat)[i];
        __half h0 = __float2half_rn(v.x), h1 = __float2half_rn(v.y);
        __half h2 = __float2half_rn(v.z), h3 = __float2half_rn(v.w);
        ((__half2*)Ahv)[2 * i]     = __half2{h0, h1};
        ((__half2*)Ahv)[2 * i + 1] = __half2{h2, h3};
        ((__half2*)Alv)[2 * i]     = __half2{
            __float2half_rn(v.x - __half2float(h0)),
            __float2half_rn(v.y - __half2float(h1))};
        ((__half2*)Alv)[2 * i + 1] = __half2{
            __float2half_rn(v.z - __half2float(h2)),
            __float2half_rn(v.w - __half2float(h3))};
    } else if (i < 1572864) {
        int j = i - 1048576;
        const float* x = (j >> 18) ? Wv2 : Wv1;
        float4 v = ((const float4*)x)[j & 262143];
        __half h0 = __float2half_rn(v.x), h1 = __float2half_rn(v.y);
        __half h2 = __float2half_rn(v.z), h3 = __float2half_rn(v.w);
        ((__half2*)Whp)[2 * j]     = __half2{h0, h1};
        ((__half2*)Whp)[2 * j + 1] = __half2{h2, h3};
        ((__half2*)Wlp)[2 * j]     = __half2{
            __float2half_rn(v.x - __half2float(h0)),
            __float2half_rn(v.y - __half2float(h1))};
        ((__half2*)Wlp)[2 * j + 1] = __half2{
            __float2half_rn(v.z - __half2float(h2)),
            __float2half_rn(v.w - __half2float(h3))};
    } else if (i < 2621440) {
        int j = i - 1572864;
        int wsel = j >> 18;
        const float* x = (wsel == 0) ? Wv3 : (wsel == 1) ? Wv4
                        : (wsel == 2) ? Ww1 : Wout;
        float4 v = ((const float4*)x)[j & 262143];
        __half2* hp = (__half2*)(Whp + 2ull * 1048576);
        hp[2 * j]     = __floats2half2_rn(v.x, v.y);
        hp[2 * j + 1] = __floats2half2_rn(v.z, v.w);
    } else if (i < 2752512) {
        int j = i - 2621440;
        float4 v = ((const float4*)w_feat)[j];
        ((__half2*)Ahw)[2 * j]     = __floats2half2_rn(v.x, v.y);
        ((__half2*)Ahw)[2 * j + 1] = __floats2half2_rn(v.z, v.w);
    }
}

// ----------------------------- HMMA GEMM core (128x128 tile) ---------------
static constexpr int T128 = 128 * 80;
static constexpr int STAGE3 = 4 * T128;
static constexpr int STAGE1 = 2 * T128;
static constexpr int SMEM3 = 2 * STAGE3;              // 81920
static constexpr int SMEM1 = 2 * STAGE1;              // 40960

template <int TERMS>
__device__ __forceinline__ void gemm_mainloop128(
    const __half* __restrict__ Ah, const __half* __restrict__ Al,
    const __half* __restrict__ Wh, const __half* __restrict__ Wl,
    uint32_t sb, int bm, int bn, int t, float acc[4][4][4])
{
    constexpr int STAGE = (TERMS == 3) ? STAGE3 : STAGE1;
    constexpr int WOFF  = (TERMS == 3) ? 2 * T128 : T128;
    int lane = t & 31, wid = t >> 5;
    int wm = (wid & 1) * 64;
    int wn = (wid >> 1) * 32;

    int r0 = t >> 2, c0 = t & 3;
    int r1 = (t + 256) >> 2;

    auto stage_load = [&](int s, int k0) {
        uint32_t base = sb + s * STAGE;
        cp_async16(base + r0 * 80 + c0 * 16, Ah + (size_t)(bm + r0) * 1024 + k0 + c0 * 8);
        cp_async16(base + r1 * 80 + c0 * 16, Ah + (size_t)(bm + r1) * 1024 + k0 + c0 * 8);
        if (TERMS == 3) {
            cp_async16(base + T128 + r0 * 80 + c0 * 16,
                       Al + (size_t)(bm + r0) * 1024 + k0 + c0 * 8);
            cp_async16(base + T128 + r1 * 80 + c0 * 16,
                       Al + (size_t)(bm + r1) * 1024 + k0 + c0 * 8);
        }
        uint32_t wb = base + WOFF;
        cp_async16(wb + r0 * 80 + c0 * 16, Wh + (size_t)(bn + r0) * 1024 + k0 + c0 * 8);
        cp_async16(wb + r1 * 80 + c0 * 16, Wh + (size_t)(bn + r1) * 1024 + k0 + c0 * 8);
        if (TERMS == 3) {
            uint32_t wlb = wb + T128;
            cp_async16(wlb + r0 * 80 + c0 * 16, Wl + (size_t)(bn + r0) * 1024 + k0 + c0 * 8);
            cp_async16(wlb + r1 * 80 + c0 * 16, Wl + (size_t)(bn + r1) * 1024 + k0 + c0 * 8);
        }
        cp_commit();
    };

    stage_load(0, 0);

    int a_r = (lane & 15);
    int a_c = (lane >> 4) << 3;
    int b4_r = (lane & 7) + ((lane >> 4) & 1) * 8;
    int b4_c = ((lane >> 3) & 1) << 3;

    for (int c = 0; c < 32; c++) {
        if (c + 1 < 32) {
            stage_load((c + 1) & 1, (c + 1) * 32);
            cp_wait1();
        } else {
            cp_wait0();
        }
        __syncthreads();

        uint32_t base = sb + (c & 1) * STAGE;
        uint32_t tAh = base, tAl = base + T128;
        uint32_t tWh = base + WOFF, tWl = tWh + T128;

#pragma unroll
        for (int kk = 0; kk < 32; kk += 16) {
            uint32_t ah[4][4], al[4][4];
#pragma unroll
            for (int mt = 0; mt < 4; mt++) {
                uint32_t off = (uint32_t)((wm + mt * 16 + a_r) * 80 + (kk + a_c) * 2);
                ldmatrix_x4(ah[mt], tAh + off);
                if (TERMS == 3) ldmatrix_x4(al[mt], tAl + off);
            }
#pragma unroll
            for (int np = 0; np < 2; np++) {
                uint32_t off = (uint32_t)((wn + np * 16 + b4_r) * 80 + (kk + b4_c) * 2);
                uint32_t bh4[4];
                ldmatrix_x4(bh4, tWh + off);
#pragma unroll
                for (int mt = 0; mt < 4; mt++) {
                    mma_f16(acc[mt][2 * np + 0], ah[mt], bh4 + 0);
                    mma_f16(acc[mt][2 * np + 1], ah[mt], bh4 + 2);
                }
                if (TERMS == 3) {
                    uint32_t bl4[4];
                    ldmatrix_x4(bl4, tWl + off);
#pragma unroll
                    for (int mt = 0; mt < 4; mt++) {
                        mma_f16(acc[mt][2 * np + 0], ah[mt], bl4 + 0);
                        mma_f16(acc[mt][2 * np + 1], ah[mt], bl4 + 2);
                    }
#pragma unroll
                    for (int mt = 0; mt < 4; mt++) {
                        mma_f16(acc[mt][2 * np + 0], al[mt], bh4 + 0);
                        mma_f16(acc[mt][2 * np + 1], al[mt], bh4 + 2);
                    }
                }
            }
        }
        __syncthreads();
    }
}

// epilogues (128-row tile)
__device__ __forceinline__ void epi_head_pair(
    float acc[4][4][4], const float* bias, __half* outh, __half* outl,
    int bm, int bn, int t, int n_per_b)
{
    int lane = t & 31, wid = t >> 5;
    int wm = (wid & 1) * 64, wn = (wid >> 1) * 32;
#pragma unroll
    for (int mt = 0; mt < 4; mt++) {
        int row_a = bm + wm + mt * 16 + (lane >> 2);
#pragma unroll
        for (int rr = 0; rr < 2; rr++) {
            int row = row_a + rr * 8;
            int b = row / n_per_b, ii = row % n_per_b;
#pragma unroll
            for (int nt = 0; nt < 4; nt++) {
                int o = bn + wn + nt * 8 + (lane & 3) * 2;
                float vx = acc[mt][nt][rr * 2 + 0] + bias[o];
                float vy = acc[mt][nt][rr * 2 + 1] + bias[o + 1];
                int h = o >> 6, d = o & 63;
                size_t idx = ((((size_t)(b * 16 + h) * n_per_b + ii) << 6) + (size_t)d) >> 1;
                __half hx = __float2half_rn(vx), hy = __float2half_rn(vy);
                __half lx = __float2half_rn(vx - __half2float(hx));
                __half ly = __float2half_rn(vy - __half2float(hy));
                ((__half2*)outh)[idx] = __half2{hx, hy};
                ((__half2*)outl)[idx] = __half2{lx, ly};
            }
        }
    }
}

__device__ __forceinline__ void epi_head_hi(
    float acc[4][4][4], const float* bias, __half* outh,
    int bm, int bn, int t, int n_per_b)
{
    int lane = t & 31, wid = t >> 5;
    int wm = (wid & 1) * 64, wn = (wid >> 1) * 32;
#pragma unroll
    for (int mt = 0; mt < 4; mt++) {
        int row_a = bm + wm + mt * 16 + (lane >> 2);
#pragma unroll
        for (int rr = 0; rr < 2; rr++) {
            int row = row_a + rr * 8;
            int b = row / n_per_b, ii = row % n_per_b;
#pragma unroll
            for (int nt = 0; nt < 4; nt++) {
                int o = bn + wn + nt * 8 + (lane & 3) * 2;
                float vx = acc[mt][nt][rr * 2 + 0] + bias[o];
                float vy = acc[mt][nt][rr * 2 + 1] + bias[o + 1];
                int h = o >> 6, d = o & 63;
                size_t idx = ((((size_t)(b * 16 + h) * n_per_b + ii) << 6) + (size_t)d) >> 1;
                ((__half2*)outh)[idx] =
                    __half2{__float2half_rn(vx), __float2half_rn(vy)};
            }
        }
    }
}

// batched projections: grid (40, 32)
__global__ void __launch_bounds__(256, 2) hmma_gemm_v4(
    const __half* __restrict__ Ah, const __half* __restrict__ Al,
    const __half* __restrict__ WhB, const __half* __restrict__ WlB,
    const __half* __restrict__ Ahw,
    const float* __restrict__ bv1, const float* __restrict__ bv2,
    const float* __restrict__ bv3, const float* __restrict__ bv4,
    const float* __restrict__ bw1,
    __half* __restrict__ Qh, __half* __restrict__ Ql,
    __half* __restrict__ Kh, __half* __restrict__ Kl,
    __half* __restrict__ V3h, __half* __restrict__ V4h,
    __half* __restrict__ W1h)
{
    extern __shared__ char smem[];
    const uint32_t sb = smem_u32(smem);
    int t = threadIdx.x;

    float acc[4][4][4];
#pragma unroll
    for (int i = 0; i < 4; i++)
#pragma unroll
        for (int j = 0; j < 4; j++)
#pragma unroll
            for (int k = 0; k < 4; k++) acc[i][j][k] = 0.f;

    if (blockIdx.x >= 32) {
        if (blockIdx.y >= 4) return;
        int bn = (blockIdx.x - 32) * 128;
        int bm = blockIdx.y * 128;
        gemm_mainloop128<1>(Ahw, nullptr, WhB + 4ull * 1048576, nullptr,
                            sb, bm, bn, t, acc);
        epi_head_hi(acc, bw1, W1h, bm, bn, t, 128);
        return;
    }

    int wsel = blockIdx.x & 3;
    int bn = (blockIdx.x >> 2) * 128;
    int bm = blockIdx.y * 128;
    const __half* Wh = WhB + (size_t)wsel * 1048576;

    if (wsel < 2) {
        const __half* Wl = WlB + (size_t)wsel * 1048576;
        gemm_mainloop128<3>(Ah, Al, Wh, Wl, sb, bm, bn, t, acc);
        if (wsel == 0) epi_head_pair(acc, bv1, Qh, Ql, bm, bn, t, 1024);
        else           epi_head_pair(acc, bv2, Kh, Kl, bm, bn, t, 1024);
    } else {
        gemm_mainloop128<1>(Ah, nullptr, Wh, nullptr, sb, bm, bn, t, acc);
        if (wsel == 2) epi_head_hi(acc, bv3, V3h, bm, bn, t, 1024);
        else           epi_head_hi(acc, bv4, V4h, bm, bn, t, 1024);
    }
}

__global__ void __launch_bounds__(256, 2) hmma_gemm_out(
    const __half* __restrict__ Ah, const __half* __restrict__ Wh,
    const float* __restrict__ bias, float* __restrict__ outf)
{
    extern __shared__ char smem[];
    const uint32_t sb = smem_u32(smem);
    int t = threadIdx.x;
    int bn = blockIdx.x * 128, bm = blockIdx.y * 128;
    float acc[4][4][4];
#pragma unroll
    for (int i = 0; i < 4; i++)
#pragma unroll
        for (int j = 0; j < 4; j++)
#pragma unroll
            for (int k = 0; k < 4; k++) acc[i][j][k] = 0.f;
    gemm_mainloop128<1>(Ah, nullptr, Wh, nullptr, sb, bm, bn, t, acc);

    int lane = t & 31, wid = t >> 5;
    int wm = (wid & 1) * 64, wn = (wid >> 1) * 32;
#pragma unroll
    for (int mt = 0; mt < 4; mt++) {
        int row_a = bm + wm + mt * 16 + (lane >> 2);
#pragma unroll
        for (int rr = 0; rr < 2; rr++) {
            int row = row_a + rr * 8;
#pragma unroll
            for (int nt = 0; nt < 4; nt++) {
                int o = bn + wn + nt * 8 + (lane & 3) * 2;
                float vx = acc[mt][nt][rr * 2 + 0] + bias[o];
                float vy = acc[mt][nt][rr * 2 + 1] + bias[o + 1];
                *(float2*)&outf[(size_t)row * 1024 + o] = float2{vx, vy};
            }
        }
    }
}

// ---------------------------------------------------------------------------
// HMMA cross scores (1-term), one-shot K=64
// ---------------------------------------------------------------------------
static constexpr int XPITCH = 144;
static constexpr int X_T = 128 * XPITCH;
static constexpr int XS_SMEM = 2 * X_T;

__global__ void __launch_bounds__(256) cross_scores_hmma(
    const __half* __restrict__ W1h,
    const __half* __restrict__ V3h, float* __restrict__ S)
{
    extern __shared__ char smem[];
    const uint32_t sb = smem_u32(smem);
    int t = threadIdx.x, lane = t & 31, wid = t >> 5;
    int vt = blockIdx.x, bh = blockIdx.y;

    const __half* a_h = W1h + (size_t)bh * 8192;
    const __half* b_h = V3h + (size_t)bh * 65536 + (size_t)vt * 8192;

#pragma unroll
    for (int it = 0; it < 4; it++) {
        int ch = t + it * 256;
        int row = ch >> 3, cc = ch & 7;
        size_t g = (size_t)row * 64 + cc * 8;
        uint32_t d = (uint32_t)(row * XPITCH + cc * 16);
        cp_async16(sb + 0 * X_T + d, a_h + g);
        cp_async16(sb + 1 * X_T + d, b_h + g);
    }
    cp_commit();
    cp_wait0();
    __syncthreads();

    int wm = (wid & 1) * 64, wn = (wid >> 1) * 32;
    int a_r = lane & 15, a_c = (lane >> 4) << 3;
    int b4_r = (lane & 7) + ((lane >> 4) & 1) * 8;
    int b4_c = ((lane >> 3) & 1) << 3;

    float acc[4][4][4];
#pragma unroll
    for (int i = 0; i < 4; i++)
#pragma unroll
        for (int j = 0; j < 4; j++)
#pragma unroll
            for (int k = 0; k < 4; k++) acc[i][j][k] = 0.f;

#pragma unroll
    for (int ks = 0; ks < 4; ks++) {
        uint32_t ah[4][4];
#pragma unroll
        for (int mt = 0; mt < 4; mt++) {
            uint32_t off = (uint32_t)((wm + mt * 16 + a_r) * XPITCH + (ks * 16 + a_c) * 2);
            ldmatrix_x4(ah[mt], sb + 0 * X_T + off);
        }
#pragma unroll
        for (int np = 0; np < 2; np++) {
            uint32_t off = (uint32_t)((wn + np * 16 + b4_r) * XPITCH + (ks * 16 + b4_c) * 2);
            uint32_t bh4[4];
            ldmatrix_x4(bh4, sb + 1 * X_T + off);
#pragma unroll
            for (int mt = 0; mt < 4; mt++) {
                mma_f16(acc[mt][2 * np + 0], ah[mt], bh4 + 0);
                mma_f16(acc[mt][2 * np + 1], ah[mt], bh4 + 2);
            }
        }
    }

    float* Sb = S + (size_t)bh * 131072;
#pragma unroll
    for (int mt = 0; mt < 4; mt++) {
        int row_a = wm + mt * 16 + (lane >> 2);
#pragma unroll
        for (int rr = 0; rr < 2; rr++) {
            int w = row_a + rr * 8;
#pragma unroll
            for (int nt = 0; nt < 4; nt++) {
                int v = vt * 128 + wn + nt * 8 + (lane & 3) * 2;
                *(float2*)&Sb[(size_t)w * 1024 + v] =
                    float2{acc[mt][nt][rr * 2 + 0], acc[mt][nt][rr * 2 + 1]};
            }
        }
    }
}

// ---------------------------------------------------------------------------
// Cross reduction, two wide launches.
// Pass 1: per-row max & inv-sum. grid 512 (8 blocks/bh, 16 rows each).
// ---------------------------------------------------------------------------
__global__ void __launch_bounds__(256) cross_rowstats(
    const float* __restrict__ S, float* __restrict__ sm, float* __restrict__ siv)
{
    int bh = blockIdx.x >> 3;
    int r0 = (blockIdx.x & 7) * 16;
    int lane = threadIdx.x & 31, w = threadIdx.x >> 5;

#pragma unroll
    for (int rr = 0; rr < 2; rr++) {
        int r = r0 + w * 2 + rr;
        const float4* p = (const float4*)(S + (size_t)bh * 131072 + (size_t)r * 1024);
        float mx = -1e30f;
#pragma unroll
        for (int j = 0; j < 8; j++) {
            float4 v = p[lane + j * 32];
            mx = fmaxf(fmaxf(mx, fmaxf(v.x, v.y)), fmaxf(v.z, v.w));
        }
#pragma unroll
        for (int o = 16; o; o >>= 1) mx = fmaxf(mx, __shfl_xor_sync(0xffffffffu, mx, o));
        float sum = 0.f;
#pragma unroll
        for (int j = 0; j < 8; j++) {
            float4 v = p[lane + j * 32];
            sum += __expf(v.x - mx) + __expf(v.y - mx)
                 + __expf(v.z - mx) + __expf(v.w - mx);
        }
#pragma unroll
        for (int o = 16; o; o >>= 1) sum += __shfl_xor_sync(0xffffffffu, sum, o);
        if (lane == 0) { sm[bh * 128 + r] = mx; siv[bh * 128 + r] = 1.f / sum; }
    }
}

// Pass 2: column accumulation. grid (64, 4), block covers 256 columns.
__global__ void __launch_bounds__(256) cross_colsum2(
    const float* __restrict__ S, const float* __restrict__ sm,
    const float* __restrict__ siv, float* __restrict__ cross)
{
    int bh = blockIdx.x;
    int t = threadIdx.x;
    int col = blockIdx.y * 256 + t;
    __shared__ float s_m[128], s_iv[128];
    if (t < 128) { s_m[t] = sm[bh * 128 + t]; s_iv[t] = siv[bh * 128 + t]; }
    __syncthreads();

    const float* Sb = S + (size_t)bh * 131072 + col;
    float a = 0.f;
#pragma unroll 4
    for (int r = 0; r < 128; r++)
        a += __expf(Sb[(size_t)r * 1024] - s_m[r]) * s_iv[r];
    cross[(size_t)bh * 1024 + col] = a;
}

// ---------------------------------------------------------------------------
// HMMA flash self-attention: QK 3-term, PV 1-term; x4 LDSM; 2 CTAs/SM.
// ---------------------------------------------------------------------------
static constexpr int APITCH = 144;
static constexpr int AQ_BYTES  = 128 * APITCH;
static constexpr int AKV_T     = 64 * APITCH;
static constexpr int AKV_BUF   = 3 * AKV_T + 256;
static constexpr int AKV_BASE  = 2 * AQ_BYTES;
static constexpr int ATTN_SMEM = AKV_BASE + 2 * AKV_BUF;

__global__ void __launch_bounds__(256, 2) attn_hmma(
    const __half* __restrict__ Qh_g, const __half* __restrict__ Ql_g,
    const __half* __restrict__ Kh_g, const __half* __restrict__ Kl_g,
    const __half* __restrict__ Vh_g,
    const float* __restrict__ cross,
    __half* __restrict__ Ch)
{
    extern __shared__ char smem[];
    const uint32_t sb = smem_u32(smem);
    int t = threadIdx.x;
    int lane = t & 31, w = t >> 5;
    int bh = blockIdx.y, qt = blockIdx.x;
    int b = bh >> 4, h = bh & 15;

    const __half* qh_g = Qh_g + (size_t)bh * 65536 + (size_t)qt * 8192;
    const __half* ql_g = Ql_g + (size_t)bh * 65536 + (size_t)qt * 8192;
    const __half* kh_g = Kh_g + (size_t)bh * 65536;
    const __half* kl_g = Kl_g + (size_t)bh * 65536;
    const __half* vh_g = Vh_g + (size_t)bh * 65536;
    const float* cr = cross + (size_t)bh * 1024;

    {
#pragma unroll
        for (int it = 0; it < 4; it++) {
            int ch = t + it * 256;
            int row = ch >> 3, cc = ch & 7;
            cp_async16(sb + row * APITCH + cc * 16, qh_g + (size_t)row * 64 + cc * 8);
            cp_async16(sb + AQ_BYTES + row * APITCH + cc * 16,
                       ql_g + (size_t)row * 64 + cc * 8);
        }
    }

    auto stage_kv = [&](int s, int kb) {
        uint32_t base = sb + AKV_BASE + s * AKV_BUF;
        int krow0 = kb * 64;
#pragma unroll
        for (int it = 0; it < 2; it++) {
            int ch = t + it * 256;
            int row = ch >> 3, cc = ch & 7;
            size_t g = (size_t)(krow0 + row) * 64 + cc * 8;
            uint32_t d = base + row * APITCH + cc * 16;
            cp_async16(d + 0 * AKV_T, kh_g + g);
            cp_async16(d + 1 * AKV_T, kl_g + g);
            cp_async16(d + 2 * AKV_T, vh_g + g);
        }
        if (t < 16) cp_async16(base + 3 * AKV_T + t * 16, cr + kb * 64 + t * 4);
        cp_commit();
    };

    stage_kv(0, 0);
    cp_wait0();
    __syncthreads();

    uint32_t qh[4][4], ql[4][4];
    {
        int a_r = w * 16 + (lane & 15);
        int a_c = (lane >> 4) << 3;
#pragma unroll
        for (int ks = 0; ks < 4; ks++) {
            uint32_t off = (uint32_t)(a_r * APITCH + (ks * 16 + a_c) * 2);
            ldmatrix_x4(qh[ks], sb + off);
            ldmatrix_x4(ql[ks], sb + AQ_BYTES + off);
        }
    }

    float o[8][4];
#pragma unroll
    for (int i = 0; i < 8; i++)
#pragma unroll
        for (int j = 0; j < 4; j++) o[i][j] = 0.f;
    float m0 = -1e30f, m1 = -1e30f, l0 = 0.f, l1 = 0.f;

    int c2 = (lane & 3) * 2;
    int b4_r = (lane & 7) + ((lane >> 4) & 1) * 8;
    int b4_c = ((lane >> 3) & 1) << 3;
    int v_r4 = (lane & 7) + ((lane >> 3) & 1) * 8;
    int v_csel = (lane >> 4) & 1;

    for (int kb = 0; kb < 16; kb++) {
        if (kb + 1 < 16) stage_kv((kb + 1) & 1, kb + 1);

        uint32_t kvb = sb + AKV_BASE + (kb & 1) * AKV_BUF;
        const float* crs = (const float*)(smem + AKV_BASE + (kb & 1) * AKV_BUF + 3 * AKV_T);

        float s[8][4];
#pragma unroll
        for (int nt = 0; nt < 8; nt++) {
            float b0 = crs[nt * 8 + c2];
            float b1 = crs[nt * 8 + c2 + 1];
            s[nt][0] = b0; s[nt][1] = b1; s[nt][2] = b0; s[nt][3] = b1;
        }

#pragma unroll
        for (int ks = 0; ks < 4; ks++) {
#pragma unroll
            for (int ntp = 0; ntp < 4; ntp++) {
                int nt0 = 2 * ntp, nt1 = nt0 + 1;
                uint32_t off = (uint32_t)((ntp * 16 + b4_r) * APITCH + (ks * 16 + b4_c) * 2);
                uint32_t kh4[4], kl4[4];
                ldmatrix_x4(kh4, kvb + off);
                ldmatrix_x4(kl4, kvb + AKV_T + off);
                mma_f16(s[nt0], qh[ks], kh4 + 0);
                mma_f16(s[nt1], qh[ks], kh4 + 2);
                mma_f16(s[nt0], qh[ks], kl4 + 0);
                mma_f16(s[nt1], qh[ks], kl4 + 2);
                mma_f16(s[nt0], ql[ks], kh4 + 0);
                mma_f16(s[nt1], ql[ks], kh4 + 2);
            }
        }

        float mx0 = -1e30f, mx1 = -1e30f;
#pragma unroll
        for (int nt = 0; nt < 8; nt++) {
            mx0 = fmaxf(mx0, fmaxf(s[nt][0], s[nt][1]));
            mx1 = fmaxf(mx1, fmaxf(s[nt][2], s[nt][3]));
        }
        mx0 = fmaxf(mx0, __shfl_xor_sync(0xffffffffu, mx0, 1));
        mx0 = fmaxf(mx0, __shfl_xor_sync(0xffffffffu, mx0, 2));
        mx1 = fmaxf(mx1, __shfl_xor_sync(0xffffffffu, mx1, 1));
        mx1 = fmaxf(mx1, __shfl_xor_sync(0xffffffffu, mx1, 2));
        float mn0 = fmaxf(m0, mx0), mn1 = fmaxf(m1, mx1);
        float sc0 = __expf(m0 - mn0), sc1 = __expf(m1 - mn1);
        m0 = mn0; m1 = mn1;

        float rs0 = 0.f, rs1 = 0.f;
        uint32_t ph0[8], ph1[8];
#pragma unroll
        for (int nt = 0; nt < 8; nt++) {
            float p0 = __expf(s[nt][0] - mn0);
            float p1 = __expf(s[nt][1] - mn0);
            float p2 = __expf(s[nt][2] - mn1);
            float p3 = __expf(s[nt][3] - mn1);
            rs0 += p0 + p1; rs1 += p2 + p3;
            __half2 hA = __floats2half2_rn(p0, p1);
            __half2 hB = __floats2half2_rn(p2, p3);
            ph0[nt] = *(uint32_t*)&hA;
            ph1[nt] = *(uint32_t*)&hB;
        }
        rs0 += __shfl_xor_sync(0xffffffffu, rs0, 1);
        rs0 += __shfl_xor_sync(0xffffffffu, rs0, 2);
        rs1 += __shfl_xor_sync(0xffffffffu, rs1, 1);
        rs1 += __shfl_xor_sync(0xffffffffu, rs1, 2);
        l0 = l0 * sc0 + rs0;
        l1 = l1 * sc1 + rs1;
#pragma unroll
        for (int nt = 0; nt < 8; nt++) {
            o[nt][0] *= sc0; o[nt][1] *= sc0;
            o[nt][2] *= sc1; o[nt][3] *= sc1;
        }

#pragma unroll
        for (int kt = 0; kt < 4; kt++) {
            uint32_t ah[4] = {ph0[2 * kt], ph1[2 * kt], ph0[2 * kt + 1], ph1[2 * kt + 1]};
#pragma unroll
            for (int ntp = 0; ntp < 4; ntp++) {
                int nt0 = 2 * ntp, nt1 = nt0 + 1;
                uint32_t voff = (uint32_t)((kt * 16 + v_r4) * APITCH
                                           + (2 * ntp + v_csel) * 16);
                uint32_t vh4[4];
                ldmatrix_x4_trans(vh4, kvb + 2 * AKV_T + voff);
                mma_f16(o[nt0], ah, vh4 + 0);
                mma_f16(o[nt1], ah, vh4 + 2);
            }
        }

        if (kb + 1 < 16) {
            cp_wait0();
            __syncthreads();
        }
    }

    float inv0 = 1.f / l0, inv1 = 1.f / l1;
    int row0 = qt * 128 + w * 16 + (lane >> 2);
    __half2* Ch2 = (__half2*)Ch;
#pragma unroll
    for (int nt = 0; nt < 8; nt++) {
        int d = nt * 8 + c2;
        {
            float x0 = o[nt][0] * inv0, x1 = o[nt][1] * inv0;
            size_t idx = (((size_t)b * 1024 + row0) * 1024 + h * 64 + d) >> 1;
            Ch2[idx] = __floats2half2_rn(x0, x1);
        }
        {
            float x0 = o[nt][2] * inv1, x1 = o[nt][3] * inv1;
            size_t idx = (((size_t)b * 1024 + row0 + 8) * 1024 + h * 64 + d) >> 1;
            Ch2[idx] = __floats2half2_rn(x0, x1);
        }
    }
}

// ---------------------------------------------------------------------------
// Launch
// ---------------------------------------------------------------------------
extern "C" void kernel_launch(void* const* d_in, const int* in_sizes, int n_in,
                              void* d_out, int out_size)
{
    const float* w_feat = (const float*)d_in[0];
    const float* v_feat = (const float*)d_in[1];
    const float* Ww1  = (const float*)d_in[2];
    const float* bw1  = (const float*)d_in[3];
    const float* Wv1  = (const float*)d_in[4];
    const float* bv1  = (const float*)d_in[5];
    const float* Wv2  = (const float*)d_in[6];
    const float* bv2  = (const float*)d_in[7];
    const float* Wv3  = (const float*)d_in[8];
    const float* bv3  = (const float*)d_in[9];
    const float* Wv4  = (const float*)d_in[10];
    const float* bv4  = (const float*)d_in[11];
    const float* Wout = (const float*)d_in[12];
    const float* bout = (const float*)d_in[13];
    float* out = (float*)d_out;

    float *Sp, *crp, *smp, *sivp;
    cudaGetSymbolAddress((void**)&Sp,  g_S);
    cudaGetSymbolAddress((void**)&crp, g_cr);
    cudaGetSymbolAddress((void**)&smp, g_sm);
    cudaGetSymbolAddress((void**)&sivp, g_siv);

    __half *Qh, *Ql, *Kh, *Kl, *V4h, *V3h, *W1h;
    cudaGetSymbolAddress((void**)&Qh,  g_Qh);
    cudaGetSymbolAddress((void**)&Ql,  g_Ql);
    cudaGetSymbolAddress((void**)&Kh,  g_Kh);
    cudaGetSymbolAddress((void**)&Kl,  g_Kl);
    cudaGetSymbolAddress((void**)&V4h, g_V4h);
    cudaGetSymbolAddress((void**)&V3h, g_V3h);
    cudaGetSymbolAddress((void**)&W1h, g_W1h);

    __half *Ahv, *Alv, *Ahw, *Whp, *Wlp, *Chp;
    cudaGetSymbolAddress((void**)&Ahv, g_Ahv);
    cudaGetSymbolAddress((void**)&Alv, g_Alv);
    cudaGetSymbolAddress((void**)&Ahw, g_Ahw);
    cudaGetSymbolAddress((void**)&Whp, g_Wh);
    cudaGetSymbolAddress((void**)&Wlp, g_Wl);
    cudaGetSymbolAddress((void**)&Chp, g_Ch);

    cudaFuncSetAttribute(hmma_gemm_v4, cudaFuncAttributeMaxDynamicSharedMemorySize, SMEM3);
    cudaFuncSetAttribute(hmma_gemm_out, cudaFuncAttributeMaxDynamicSharedMemorySize, SMEM1);
    cudaFuncSetAttribute(cross_scores_hmma, cudaFuncAttributeMaxDynamicSharedMemorySize, XS_SMEM);
    cudaFuncSetAttribute(attn_hmma, cudaFuncAttributeMaxDynamicSharedMemorySize, ATTN_SMEM);

    // 0: all fp32->fp16 conversions in one launch
    convert_all<<<10752, 256>>>(v_feat, w_feat, Wv1, Wv2, Wv3, Wv4, Ww1, Wout,
                                Ahv, Alv, Whp, Wlp, Ahw);

    // 1: Q/K (3t) + V3/V4 (1t) + w1 (1t) projections
    hmma_gemm_v4<<<dim3(40, 32), 256, SMEM3>>>(
        Ahv, Alv, Whp, Wlp, Ahw, bv1, bv2, bv3, bv4, bw1,
        Qh, Ql, Kh, Kl, V3h, V4h, W1h);

    // 2..4: cross-attention bias path (wide reductions)
    cross_scores_hmma<<<dim3(8, 64), 256, XS_SMEM>>>(W1h, V3h, Sp);
    cross_rowstats<<<512, 256>>>(Sp, smp, sivp);
    cross_colsum2<<<dim3(64, 4), 256>>>(Sp, smp, sivp, crp);

    // 5: flash self-attention
    attn_hmma<<<dim3(8, 64), 256, ATTN_SMEM>>>(Qh, Ql, Kh, Kl, V4h, crp, Chp);

    // 6: output projection
    hmma_gemm_out<<<dim3(8, 32), 256, SMEM1>>>(
        Chp, Whp + 5ull * 1048576, bout, out);
}

// round 17
// speedup vs baseline: 1.5595x; 1.0160x over previous
#include <cuda_runtime.h>
#include <cuda_fp16.h>
#include <cstdint>
#include <math.h>

// ---------------------------------------------------------------------------
// Shapes: bs=4, H=16, DK=64, D=1024, n_w=128, n_v=1024
// HMMA fp16, calibrated error compensation:
//   3-term: Q/K projections, Q.K^T (score path)
//   1-term: V3/V4/w1 proj, cross, P.V, out proj
// R17: single-sync GEMM chunk loop (wait->sync->prefetch->compute);
//      3-stage pipeline for 1-term GEMMs.
// ---------------------------------------------------------------------------

__device__ __forceinline__ uint32_t smem_u32(const void* p) {
    uint32_t a;
    asm("{ .reg .u64 t; cvta.to.shared.u64 t, %1; cvt.u32.u64 %0, t; }"
        : "=r"(a) : "l"(p));
    return a;
}

__device__ __forceinline__ void cp_async16(uint32_t dst, const void* src) {
    asm volatile("cp.async.cg.shared.global [%0], [%1], 16;"
                 :: "r"(dst), "l"(src) : "memory");
}
__device__ __forceinline__ void cp_commit() {
    asm volatile("cp.async.commit_group;" ::: "memory");
}
__device__ __forceinline__ void cp_wait0() {
    asm volatile("cp.async.wait_group 0;" ::: "memory");
}
__device__ __forceinline__ void cp_wait1() {
    asm volatile("cp.async.wait_group 1;" ::: "memory");
}

__device__ __forceinline__ void ldmatrix_x4(uint32_t* r, uint32_t addr) {
    asm volatile("ldmatrix.sync.aligned.m8n8.x4.shared.b16 {%0,%1,%2,%3}, [%4];"
                 : "=r"(r[0]), "=r"(r[1]), "=r"(r[2]), "=r"(r[3]) : "r"(addr));
}
__device__ __forceinline__ void ldmatrix_x4_trans(uint32_t* r, uint32_t addr) {
    asm volatile("ldmatrix.sync.aligned.m8n8.x4.trans.shared.b16 {%0,%1,%2,%3}, [%4];"
                 : "=r"(r[0]), "=r"(r[1]), "=r"(r[2]), "=r"(r[3]) : "r"(addr));
}

__device__ __forceinline__ void mma_f16(float* c, const uint32_t* a, const uint32_t* b) {
    asm volatile(
        "mma.sync.aligned.m16n8k16.row.col.f32.f16.f16.f32 "
        "{%0,%1,%2,%3}, {%4,%5,%6,%7}, {%8,%9}, {%0,%1,%2,%3};"
        : "+f"(c[0]), "+f"(c[1]), "+f"(c[2]), "+f"(c[3])
        : "r"(a[0]), "r"(a[1]), "r"(a[2]), "r"(a[3]), "r"(b[0]), "r"(b[1]));
}

// ----------------------------- scratch ------------------------------------
__device__ __align__(256) float g_S [4 * 16 * 128 * 1024];
__device__ __align__(256) float g_cr[4 * 16 * 1024];
__device__ __align__(256) float g_sm[8192], g_siv[8192];

__device__ __align__(256) __half g_Qh[4194304], g_Ql[4194304];
__device__ __align__(256) __half g_Kh[4194304], g_Kl[4194304];
__device__ __align__(256) __half g_V4h[4194304];
__device__ __align__(256) __half g_V3h[4194304];
__device__ __align__(256) __half g_W1h[524288];

__device__ __align__(256) __half g_Ahv[4194304], g_Alv[4194304];
__device__ __align__(256) __half g_Ahw[524288];
__device__ __align__(256) __half g_Wh[6 * 1048576], g_Wl[2 * 1048576];
__device__ __align__(256) __half g_Ch[4194304];

// ----------------------------- fused conversions ---------------------------
__global__ void __launch_bounds__(256) convert_all(
    const float* __restrict__ v_feat, const float* __restrict__ w_feat,
    const float* __restrict__ Wv1, const float* __restrict__ Wv2,
    const float* __restrict__ Wv3, const float* __restrict__ Wv4,
    const float* __restrict__ Ww1, const float* __restrict__ Wout,
    __half* __restrict__ Ahv, __half* __restrict__ Alv,
    __half* __restrict__ Whp, __half* __restrict__ Wlp,
    __half* __restrict__ Ahw)
{
    int i = blockIdx.x * 256 + threadIdx.x;
    if (i < 1048576) {
        float4 v = ((const float4*)v_feat)[i];
        __half h0 = __float2half_rn(v.x), h1 = __float2half_rn(v.y);
        __half h2 = __float2half_rn(v.z), h3 = __float2half_rn(v.w);
        ((__half2*)Ahv)[2 * i]     = __half2{h0, h1};
        ((__half2*)Ahv)[2 * i + 1] = __half2{h2, h3};
        ((__half2*)Alv)[2 * i]     = __half2{
            __float2half_rn(v.x - __half2float(h0)),
            __float2half_rn(v.y - __half2float(h1))};
        ((__half2*)Alv)[2 * i + 1] = __half2{
            __float2half_rn(v.z - __half2float(h2)),
            __float2half_rn(v.w - __half2float(h3))};
    } else if (i < 1572864) {
        int j = i - 1048576;
        const float* x = (j >> 18) ? Wv2 : Wv1;
        float4 v = ((const float4*)x)[j & 262143];
        __half h0 = __float2half_rn(v.x), h1 = __float2half_rn(v.y);
        __half h2 = __float2half_rn(v.z), h3 = __float2half_rn(v.w);
        ((__half2*)Whp)[2 * j]     = __half2{h0, h1};
        ((__half2*)Whp)[2 * j + 1] = __half2{h2, h3};
        ((__half2*)Wlp)[2 * j]     = __half2{
            __float2half_rn(v.x - __half2float(h0)),
            __float2half_rn(v.y - __half2float(h1))};
        ((__half2*)Wlp)[2 * j + 1] = __half2{
            __float2half_rn(v.z - __half2float(h2)),
            __float2half_rn(v.w - __half2float(h3))};
    } else if (i < 2621440) {
        int j = i - 1572864;
        int wsel = j >> 18;
        const float* x = (wsel == 0) ? Wv3 : (wsel == 1) ? Wv4
                        : (wsel == 2) ? Ww1 : Wout;
        float4 v = ((const float4*)x)[j & 262143];
        __half2* hp = (__half2*)(Whp + 2ull * 1048576);
        hp[2 * j]     = __floats2half2_rn(v.x, v.y);
        hp[2 * j + 1] = __floats2half2_rn(v.z, v.w);
    } else if (i < 2752512) {
        int j = i - 2621440;
        float4 v = ((const float4*)w_feat)[j];
        ((__half2*)Ahw)[2 * j]     = __floats2half2_rn(v.x, v.y);
        ((__half2*)Ahw)[2 * j + 1] = __floats2half2_rn(v.z, v.w);
    }
}

// ----------------------------- HMMA GEMM core (128x128 tile) ---------------
static constexpr int T128 = 128 * 80;
static constexpr int STAGE3 = 4 * T128;               // Ah Al Wh Wl
static constexpr int STAGE1 = 2 * T128;               // Ah Wh
static constexpr int SMEM3 = 2 * STAGE3;              // 81920 (2-stage)
static constexpr int SMEM1 = 3 * STAGE1;              // 61440 (3-stage)

template <int TERMS>
__device__ __forceinline__ void gemm_mainloop128(
    const __half* __restrict__ Ah, const __half* __restrict__ Al,
    const __half* __restrict__ Wh, const __half* __restrict__ Wl,
    uint32_t sb, int bm, int bn, int t, float acc[4][4][4])
{
    constexpr int STAGES = (TERMS == 3) ? 2 : 3;
    constexpr int STAGE  = (TERMS == 3) ? STAGE3 : STAGE1;
    constexpr int WOFF   = (TERMS == 3) ? 2 * T128 : T128;
    int lane = t & 31, wid = t >> 5;
    int wm = (wid & 1) * 64;
    int wn = (wid >> 1) * 32;

    int r0 = t >> 2, c0 = t & 3;
    int r1 = (t + 256) >> 2;

    auto stage_load = [&](int s, int k0) {
        uint32_t base = sb + s * STAGE;
        cp_async16(base + r0 * 80 + c0 * 16, Ah + (size_t)(bm + r0) * 1024 + k0 + c0 * 8);
        cp_async16(base + r1 * 80 + c0 * 16, Ah + (size_t)(bm + r1) * 1024 + k0 + c0 * 8);
        if (TERMS == 3) {
            cp_async16(base + T128 + r0 * 80 + c0 * 16,
                       Al + (size_t)(bm + r0) * 1024 + k0 + c0 * 8);
            cp_async16(base + T128 + r1 * 80 + c0 * 16,
                       Al + (size_t)(bm + r1) * 1024 + k0 + c0 * 8);
        }
        uint32_t wb = base + WOFF;
        cp_async16(wb + r0 * 80 + c0 * 16, Wh + (size_t)(bn + r0) * 1024 + k0 + c0 * 8);
        cp_async16(wb + r1 * 80 + c0 * 16, Wh + (size_t)(bn + r1) * 1024 + k0 + c0 * 8);
        if (TERMS == 3) {
            uint32_t wlb = wb + T128;
            cp_async16(wlb + r0 * 80 + c0 * 16, Wl + (size_t)(bn + r0) * 1024 + k0 + c0 * 8);
            cp_async16(wlb + r1 * 80 + c0 * 16, Wl + (size_t)(bn + r1) * 1024 + k0 + c0 * 8);
        }
        cp_commit();
    };

    // prologue: fill STAGES-1 buffers
#pragma unroll
    for (int s = 0; s < STAGES - 1; s++) stage_load(s, s * 32);

    int a_r = (lane & 15);
    int a_c = (lane >> 4) << 3;
    int b4_r = (lane & 7) + ((lane >> 4) & 1) * 8;
    int b4_c = ((lane >> 3) & 1) << 3;

    for (int c = 0; c < 32; c++) {
        // wait for group c (allow STAGES-2 newer groups pending)
        if (STAGES == 2) cp_wait0(); else cp_wait1();
        __syncthreads();   // visibility of group c + all warps done with prev buffer

        // prefetch chunk c+STAGES-1 into the buffer last read at iter c-1
        int nc = c + STAGES - 1;
        if (nc < 32) stage_load(nc % STAGES, nc * 32);
        else         cp_commit();          // empty group keeps wait accounting exact

        uint32_t base = sb + (c % STAGES) * STAGE;
        uint32_t tAh = base, tAl = base + T128;
        uint32_t tWh = base + WOFF, tWl = tWh + T128;

#pragma unroll
        for (int kk = 0; kk < 32; kk += 16) {
            uint32_t ah[4][4], al[4][4];
#pragma unroll
            for (int mt = 0; mt < 4; mt++) {
                uint32_t off = (uint32_t)((wm + mt * 16 + a_r) * 80 + (kk + a_c) * 2);
                ldmatrix_x4(ah[mt], tAh + off);
                if (TERMS == 3) ldmatrix_x4(al[mt], tAl + off);
            }
#pragma unroll
            for (int np = 0; np < 2; np++) {
                uint32_t off = (uint32_t)((wn + np * 16 + b4_r) * 80 + (kk + b4_c) * 2);
                uint32_t bh4[4];
                ldmatrix_x4(bh4, tWh + off);
#pragma unroll
                for (int mt = 0; mt < 4; mt++) {
                    mma_f16(acc[mt][2 * np + 0], ah[mt], bh4 + 0);
                    mma_f16(acc[mt][2 * np + 1], ah[mt], bh4 + 2);
                }
                if (TERMS == 3) {
                    uint32_t bl4[4];
                    ldmatrix_x4(bl4, tWl + off);
#pragma unroll
                    for (int mt = 0; mt < 4; mt++) {
                        mma_f16(acc[mt][2 * np + 0], ah[mt], bl4 + 0);
                        mma_f16(acc[mt][2 * np + 1], ah[mt], bl4 + 2);
                    }
#pragma unroll
                    for (int mt = 0; mt < 4; mt++) {
                        mma_f16(acc[mt][2 * np + 0], al[mt], bh4 + 0);
                        mma_f16(acc[mt][2 * np + 1], al[mt], bh4 + 2);
                    }
                }
            }
        }
        // no end-of-chunk sync: next iteration's wait+sync protects buffer reuse
    }
    __syncthreads();   // final: all warps done before epilogue reuses nothing (safety)
}

// epilogues (128-row tile)
__device__ __forceinline__ void epi_head_pair(
    float acc[4][4][4], const float* bias, __half* outh, __half* outl,
    int bm, int bn, int t, int n_per_b)
{
    int lane = t & 31, wid = t >> 5;
    int wm = (wid & 1) * 64, wn = (wid >> 1) * 32;
#pragma unroll
    for (int mt = 0; mt < 4; mt++) {
        int row_a = bm + wm + mt * 16 + (lane >> 2);
#pragma unroll
        for (int rr = 0; rr < 2; rr++) {
            int row = row_a + rr * 8;
            int b = row / n_per_b, ii = row % n_per_b;
#pragma unroll
            for (int nt = 0; nt < 4; nt++) {
                int o = bn + wn + nt * 8 + (lane & 3) * 2;
                float vx = acc[mt][nt][rr * 2 + 0] + bias[o];
                float vy = acc[mt][nt][rr * 2 + 1] + bias[o + 1];
                int h = o >> 6, d = o & 63;
                size_t idx = ((((size_t)(b * 16 + h) * n_per_b + ii) << 6) + (size_t)d) >> 1;
                __half hx = __float2half_rn(vx), hy = __float2half_rn(vy);
                __half lx = __float2half_rn(vx - __half2float(hx));
                __half ly = __float2half_rn(vy - __half2float(hy));
                ((__half2*)outh)[idx] = __half2{hx, hy};
                ((__half2*)outl)[idx] = __half2{lx, ly};
            }
        }
    }
}

__device__ __forceinline__ void epi_head_hi(
    float acc[4][4][4], const float* bias, __half* outh,
    int bm, int bn, int t, int n_per_b)
{
    int lane = t & 31, wid = t >> 5;
    int wm = (wid & 1) * 64, wn = (wid >> 1) * 32;
#pragma unroll
    for (int mt = 0; mt < 4; mt++) {
        int row_a = bm + wm + mt * 16 + (lane >> 2);
#pragma unroll
        for (int rr = 0; rr < 2; rr++) {
            int row = row_a + rr * 8;
            int b = row / n_per_b, ii = row % n_per_b;
#pragma unroll
            for (int nt = 0; nt < 4; nt++) {
                int o = bn + wn + nt * 8 + (lane & 3) * 2;
                float vx = acc[mt][nt][rr * 2 + 0] + bias[o];
                float vy = acc[mt][nt][rr * 2 + 1] + bias[o + 1];
                int h = o >> 6, d = o & 63;
                size_t idx = ((((size_t)(b * 16 + h) * n_per_b + ii) << 6) + (size_t)d) >> 1;
                ((__half2*)outh)[idx] =
                    __half2{__float2half_rn(vx), __float2half_rn(vy)};
            }
        }
    }
}

// batched projections: grid (40, 32)
__global__ void __launch_bounds__(256, 2) hmma_gemm_v4(
    const __half* __restrict__ Ah, const __half* __restrict__ Al,
    const __half* __restrict__ WhB, const __half* __restrict__ WlB,
    const __half* __restrict__ Ahw,
    const float* __restrict__ bv1, const float* __restrict__ bv2,
    const float* __restrict__ bv3, const float* __restrict__ bv4,
    const float* __restrict__ bw1,
    __half* __restrict__ Qh, __half* __restrict__ Ql,
    __half* __restrict__ Kh, __half* __restrict__ Kl,
    __half* __restrict__ V3h, __half* __restrict__ V4h,
    __half* __restrict__ W1h)
{
    extern __shared__ char smem[];
    const uint32_t sb = smem_u32(smem);
    int t = threadIdx.x;

    float acc[4][4][4];
#pragma unroll
    for (int i = 0; i < 4; i++)
#pragma unroll
        for (int j = 0; j < 4; j++)
#pragma unroll
            for (int k = 0; k < 4; k++) acc[i][j][k] = 0.f;

    if (blockIdx.x >= 32) {
        if (blockIdx.y >= 4) return;
        int bn = (blockIdx.x - 32) * 128;
        int bm = blockIdx.y * 128;
        gemm_mainloop128<1>(Ahw, nullptr, WhB + 4ull * 1048576, nullptr,
                            sb, bm, bn, t, acc);
        epi_head_hi(acc, bw1, W1h, bm, bn, t, 128);
        return;
    }

    int wsel = blockIdx.x & 3;
    int bn = (blockIdx.x >> 2) * 128;
    int bm = blockIdx.y * 128;
    const __half* Wh = WhB + (size_t)wsel * 1048576;

    if (wsel < 2) {
        const __half* Wl = WlB + (size_t)wsel * 1048576;
        gemm_mainloop128<3>(Ah, Al, Wh, Wl, sb, bm, bn, t, acc);
        if (wsel == 0) epi_head_pair(acc, bv1, Qh, Ql, bm, bn, t, 1024);
        else           epi_head_pair(acc, bv2, Kh, Kl, bm, bn, t, 1024);
    } else {
        gemm_mainloop128<1>(Ah, nullptr, Wh, nullptr, sb, bm, bn, t, acc);
        if (wsel == 2) epi_head_hi(acc, bv3, V3h, bm, bn, t, 1024);
        else           epi_head_hi(acc, bv4, V4h, bm, bn, t, 1024);
    }
}

__global__ void __launch_bounds__(256, 2) hmma_gemm_out(
    const __half* __restrict__ Ah, const __half* __restrict__ Wh,
    const float* __restrict__ bias, float* __restrict__ outf)
{
    extern __shared__ char smem[];
    const uint32_t sb = smem_u32(smem);
    int t = threadIdx.x;
    int bn = blockIdx.x * 128, bm = blockIdx.y * 128;
    float acc[4][4][4];
#pragma unroll
    for (int i = 0; i < 4; i++)
#pragma unroll
        for (int j = 0; j < 4; j++)
#pragma unroll
            for (int k = 0; k < 4; k++) acc[i][j][k] = 0.f;
    gemm_mainloop128<1>(Ah, nullptr, Wh, nullptr, sb, bm, bn, t, acc);

    int lane = t & 31, wid = t >> 5;
    int wm = (wid & 1) * 64, wn = (wid >> 1) * 32;
#pragma unroll
    for (int mt = 0; mt < 4; mt++) {
        int row_a = bm + wm + mt * 16 + (lane >> 2);
#pragma unroll
        for (int rr = 0; rr < 2; rr++) {
            int row = row_a + rr * 8;
#pragma unroll
            for (int nt = 0; nt < 4; nt++) {
                int o = bn + wn + nt * 8 + (lane & 3) * 2;
                float vx = acc[mt][nt][rr * 2 + 0] + bias[o];
                float vy = acc[mt][nt][rr * 2 + 1] + bias[o + 1];
                *(float2*)&outf[(size_t)row * 1024 + o] = float2{vx, vy};
            }
        }
    }
}

// ---------------------------------------------------------------------------
// HMMA cross scores (1-term), one-shot K=64
// ---------------------------------------------------------------------------
static constexpr int XPITCH = 144;
static constexpr int X_T = 128 * XPITCH;
static constexpr int XS_SMEM = 2 * X_T;

__global__ void __launch_bounds__(256) cross_scores_hmma(
    const __half* __restrict__ W1h,
    const __half* __restrict__ V3h, float* __restrict__ S)
{
    extern __shared__ char smem[];
    const uint32_t sb = smem_u32(smem);
    int t = threadIdx.x, lane = t & 31, wid = t >> 5;
    int vt = blockIdx.x, bh = blockIdx.y;

    const __half* a_h = W1h + (size_t)bh * 8192;
    const __half* b_h = V3h + (size_t)bh * 65536 + (size_t)vt * 8192;

#pragma unroll
    for (int it = 0; it < 4; it++) {
        int ch = t + it * 256;
        int row = ch >> 3, cc = ch & 7;
        size_t g = (size_t)row * 64 + cc * 8;
        uint32_t d = (uint32_t)(row * XPITCH + cc * 16);
        cp_async16(sb + 0 * X_T + d, a_h + g);
        cp_async16(sb + 1 * X_T + d, b_h + g);
    }
    cp_commit();
    cp_wait0();
    __syncthreads();

    int wm = (wid & 1) * 64, wn = (wid >> 1) * 32;
    int a_r = lane & 15, a_c = (lane >> 4) << 3;
    int b4_r = (lane & 7) + ((lane >> 4) & 1) * 8;
    int b4_c = ((lane >> 3) & 1) << 3;

    float acc[4][4][4];
#pragma unroll
    for (int i = 0; i < 4; i++)
#pragma unroll
        for (int j = 0; j < 4; j++)
#pragma unroll
            for (int k = 0; k < 4; k++) acc[i][j][k] = 0.f;

#pragma unroll
    for (int ks = 0; ks < 4; ks++) {
        uint32_t ah[4][4];
#pragma unroll
        for (int mt = 0; mt < 4; mt++) {
            uint32_t off = (uint32_t)((wm + mt * 16 + a_r) * XPITCH + (ks * 16 + a_c) * 2);
            ldmatrix_x4(ah[mt], sb + 0 * X_T + off);
        }
#pragma unroll
        for (int np = 0; np < 2; np++) {
            uint32_t off = (uint32_t)((wn + np * 16 + b4_r) * XPITCH + (ks * 16 + b4_c) * 2);
            uint32_t bh4[4];
            ldmatrix_x4(bh4, sb + 1 * X_T + off);
#pragma unroll
            for (int mt = 0; mt < 4; mt++) {
                mma_f16(acc[mt][2 * np + 0], ah[mt], bh4 + 0);
                mma_f16(acc[mt][2 * np + 1], ah[mt], bh4 + 2);
            }
        }
    }

    float* Sb = S + (size_t)bh * 131072;
#pragma unroll
    for (int mt = 0; mt < 4; mt++) {
        int row_a = wm + mt * 16 + (lane >> 2);
#pragma unroll
        for (int rr = 0; rr < 2; rr++) {
            int w = row_a + rr * 8;
#pragma unroll
            for (int nt = 0; nt < 4; nt++) {
                int v = vt * 128 + wn + nt * 8 + (lane & 3) * 2;
                *(float2*)&Sb[(size_t)w * 1024 + v] =
                    float2{acc[mt][nt][rr * 2 + 0], acc[mt][nt][rr * 2 + 1]};
            }
        }
    }
}

// ---------------------------------------------------------------------------
// Cross reduction, two wide launches.
// ---------------------------------------------------------------------------
__global__ void __launch_bounds__(256) cross_rowstats(
    const float* __restrict__ S, float* __restrict__ sm, float* __restrict__ siv)
{
    int bh = blockIdx.x >> 3;
    int r0 = (blockIdx.x & 7) * 16;
    int lane = threadIdx.x & 31, w = threadIdx.x >> 5;

#pragma unroll
    for (int rr = 0; rr < 2; rr++) {
        int r = r0 + w * 2 + rr;
        const float4* p = (const float4*)(S + (size_t)bh * 131072 + (size_t)r * 1024);
        float mx = -1e30f;
#pragma unroll
        for (int j = 0; j < 8; j++) {
            float4 v = p[lane + j * 32];
            mx = fmaxf(fmaxf(mx, fmaxf(v.x, v.y)), fmaxf(v.z, v.w));
        }
#pragma unroll
        for (int o = 16; o; o >>= 1) mx = fmaxf(mx, __shfl_xor_sync(0xffffffffu, mx, o));
        float sum = 0.f;
#pragma unroll
        for (int j = 0; j < 8; j++) {
            float4 v = p[lane + j * 32];
            sum += __expf(v.x - mx) + __expf(v.y - mx)
                 + __expf(v.z - mx) + __expf(v.w - mx);
        }
#pragma unroll
        for (int o = 16; o; o >>= 1) sum += __shfl_xor_sync(0xffffffffu, sum, o);
        if (lane == 0) { sm[bh * 128 + r] = mx; siv[bh * 128 + r] = 1.f / sum; }
    }
}

__global__ void __launch_bounds__(256) cross_colsum2(
    const float* __restrict__ S, const float* __restrict__ sm,
    const float* __restrict__ siv, float* __restrict__ cross)
{
    int bh = blockIdx.x;
    int t = threadIdx.x;
    int col = blockIdx.y * 256 + t;
    __shared__ float s_m[128], s_iv[128];
    if (t < 128) { s_m[t] = sm[bh * 128 + t]; s_iv[t] = siv[bh * 128 + t]; }
    __syncthreads();

    const float* Sb = S + (size_t)bh * 131072 + col;
    float a = 0.f;
#pragma unroll 4
    for (int r = 0; r < 128; r++)
        a += __expf(Sb[(size_t)r * 1024] - s_m[r]) * s_iv[r];
    cross[(size_t)bh * 1024 + col] = a;
}

// ---------------------------------------------------------------------------
// HMMA flash self-attention: QK 3-term, PV 1-term; x4 LDSM; 2 CTAs/SM.
// ---------------------------------------------------------------------------
static constexpr int APITCH = 144;
static constexpr int AQ_BYTES  = 128 * APITCH;
static constexpr int AKV_T     = 64 * APITCH;
static constexpr int AKV_BUF   = 3 * AKV_T + 256;
static constexpr int AKV_BASE  = 2 * AQ_BYTES;
static constexpr int ATTN_SMEM = AKV_BASE + 2 * AKV_BUF;

__global__ void __launch_bounds__(256, 2) attn_hmma(
    const __half* __restrict__ Qh_g, const __half* __restrict__ Ql_g,
    const __half* __restrict__ Kh_g, const __half* __restrict__ Kl_g,
    const __half* __restrict__ Vh_g,
    const float* __restrict__ cross,
    __half* __restrict__ Ch)
{
    extern __shared__ char smem[];
    const uint32_t sb = smem_u32(smem);
    int t = threadIdx.x;
    int lane = t & 31, w = t >> 5;
    int bh = blockIdx.y, qt = blockIdx.x;
    int b = bh >> 4, h = bh & 15;

    const __half* qh_g = Qh_g + (size_t)bh * 65536 + (size_t)qt * 8192;
    const __half* ql_g = Ql_g + (size_t)bh * 65536 + (size_t)qt * 8192;
    const __half* kh_g = Kh_g + (size_t)bh * 65536;
    const __half* kl_g = Kl_g + (size_t)bh * 65536;
    const __half* vh_g = Vh_g + (size_t)bh * 65536;
    const float* cr = cross + (size_t)bh * 1024;

    {
#pragma unroll
        for (int it = 0; it < 4; it++) {
            int ch = t + it * 256;
            int row = ch >> 3, cc = ch & 7;
            cp_async16(sb + row * APITCH + cc * 16, qh_g + (size_t)row * 64 + cc * 8);
            cp_async16(sb + AQ_BYTES + row * APITCH + cc * 16,
                       ql_g + (size_t)row * 64 + cc * 8);
        }
    }

    auto stage_kv = [&](int s, int kb) {
        uint32_t base = sb + AKV_BASE + s * AKV_BUF;
        int krow0 = kb * 64;
#pragma unroll
        for (int it = 0; it < 2; it++) {
            int ch = t + it * 256;
            int row = ch >> 3, cc = ch & 7;
            size_t g = (size_t)(krow0 + row) * 64 + cc * 8;
            uint32_t d = base + row * APITCH + cc * 16;
            cp_async16(d + 0 * AKV_T, kh_g + g);
            cp_async16(d + 1 * AKV_T, kl_g + g);
            cp_async16(d + 2 * AKV_T, vh_g + g);
        }
        if (t < 16) cp_async16(base + 3 * AKV_T + t * 16, cr + kb * 64 + t * 4);
        cp_commit();
    };

    stage_kv(0, 0);
    cp_wait0();
    __syncthreads();

    uint32_t qh[4][4], ql[4][4];
    {
        int a_r = w * 16 + (lane & 15);
        int a_c = (lane >> 4) << 3;
#pragma unroll
        for (int ks = 0; ks < 4; ks++) {
            uint32_t off = (uint32_t)(a_r * APITCH + (ks * 16 + a_c) * 2);
            ldmatrix_x4(qh[ks], sb + off);
            ldmatrix_x4(ql[ks], sb + AQ_BYTES + off);
        }
    }

    float o[8][4];
#pragma unroll
    for (int i = 0; i < 8; i++)
#pragma unroll
        for (int j = 0; j < 4; j++) o[i][j] = 0.f;
    float m0 = -1e30f, m1 = -1e30f, l0 = 0.f, l1 = 0.f;

    int c2 = (lane & 3) * 2;
    int b4_r = (lane & 7) + ((lane >> 4) & 1) * 8;
    int b4_c = ((lane >> 3) & 1) << 3;
    int v_r4 = (lane & 7) + ((lane >> 3) & 1) * 8;
    int v_csel = (lane >> 4) & 1;

    for (int kb = 0; kb < 16; kb++) {
        if (kb + 1 < 16) stage_kv((kb + 1) & 1, kb + 1);

        uint32_t kvb = sb + AKV_BASE + (kb & 1) * AKV_BUF;
        const float* crs = (const float*)(smem + AKV_BASE + (kb & 1) * AKV_BUF + 3 * AKV_T);

        float s[8][4];
#pragma unroll
        for (int nt = 0; nt < 8; nt++) {
            float b0 = crs[nt * 8 + c2];
            float b1 = crs[nt * 8 + c2 + 1];
            s[nt][0] = b0; s[nt][1] = b1; s[nt][2] = b0; s[nt][3] = b1;
        }

#pragma unroll
        for (int ks = 0; ks < 4; ks++) {
#pragma unroll
            for (int ntp = 0; ntp < 4; ntp++) {
                int nt0 = 2 * ntp, nt1 = nt0 + 1;
                uint32_t off = (uint32_t)((ntp * 16 + b4_r) * APITCH + (ks * 16 + b4_c) * 2);
                uint32_t kh4[4], kl4[4];
                ldmatrix_x4(kh4, kvb + off);
                ldmatrix_x4(kl4, kvb + AKV_T + off);
                mma_f16(s[nt0], qh[ks], kh4 + 0);
                mma_f16(s[nt1], qh[ks], kh4 + 2);
                mma_f16(s[nt0], qh[ks], kl4 + 0);
                mma_f16(s[nt1], qh[ks], kl4 + 2);
                mma_f16(s[nt0], ql[ks], kh4 + 0);
                mma_f16(s[nt1], ql[ks], kh4 + 2);
            }
        }

        float mx0 = -1e30f, mx1 = -1e30f;
#pragma unroll
        for (int nt = 0; nt < 8; nt++) {
            mx0 = fmaxf(mx0, fmaxf(s[nt][0], s[nt][1]));
            mx1 = fmaxf(mx1, fmaxf(s[nt][2], s[nt][3]));
        }
        mx0 = fmaxf(mx0, __shfl_xor_sync(0xffffffffu, mx0, 1));
        mx0 = fmaxf(mx0, __shfl_xor_sync(0xffffffffu, mx0, 2));
        mx1 = fmaxf(mx1, __shfl_xor_sync(0xffffffffu, mx1, 1));
        mx1 = fmaxf(mx1, __shfl_xor_sync(0xffffffffu, mx1, 2));
        float mn0 = fmaxf(m0, mx0), mn1 = fmaxf(m1, mx1);
        float sc0 = __expf(m0 - mn0), sc1 = __expf(m1 - mn1);
        m0 = mn0; m1 = mn1;

        float rs0 = 0.f, rs1 = 0.f;
        uint32_t ph0[8], ph1[8];
#pragma unroll
        for (int nt = 0; nt < 8; nt++) {
            float p0 = __expf(s[nt][0] - mn0);
            float p1 = __expf(s[nt][1] - mn0);
            float p2 = __expf(s[nt][2] - mn1);
            float p3 = __expf(s[nt][3] - mn1);
            rs0 += p0 + p1; rs1 += p2 + p3;
            __half2 hA = __floats2half2_rn(p0, p1);
            __half2 hB = __floats2half2_rn(p2, p3);
            ph0[nt] = *(uint32_t*)&hA;
            ph1[nt] = *(uint32_t*)&hB;
        }
        rs0 += __shfl_xor_sync(0xffffffffu, rs0, 1);
        rs0 += __shfl_xor_sync(0xffffffffu, rs0, 2);
        rs1 += __shfl_xor_sync(0xffffffffu, rs1, 1);
        rs1 += __shfl_xor_sync(0xffffffffu, rs1, 2);
        l0 = l0 * sc0 + rs0;
        l1 = l1 * sc1 + rs1;
#pragma unroll
        for (int nt = 0; nt < 8; nt++) {
            o[nt][0] *= sc0; o[nt][1] *= sc0;
            o[nt][2] *= sc1; o[nt][3] *= sc1;
        }

#pragma unroll
        for (int kt = 0; kt < 4; kt++) {
            uint32_t ah[4] = {ph0[2 * kt], ph1[2 * kt], ph0[2 * kt + 1], ph1[2 * kt + 1]};
#pragma unroll
            for (int ntp = 0; ntp < 4; ntp++) {
                int nt0 = 2 * ntp, nt1 = nt0 + 1;
                uint32_t voff = (uint32_t)((kt * 16 + v_r4) * APITCH
                                           + (2 * ntp + v_csel) * 16);
                uint32_t vh4[4];
                ldmatrix_x4_trans(vh4, kvb + 2 * AKV_T + voff);
                mma_f16(o[nt0], ah, vh4 + 0);
                mma_f16(o[nt1], ah, vh4 + 2);
            }
        }

        if (kb + 1 < 16) {
            cp_wait0();
            __syncthreads();
        }
    }

    float inv0 = 1.f / l0, inv1 = 1.f / l1;
    int row0 = qt * 128 + w * 16 + (lane >> 2);
    __half2* Ch2 = (__half2*)Ch;
#pragma unroll
    for (int nt = 0; nt < 8; nt++) {
        int d = nt * 8 + c2;
        {
            float x0 = o[nt][0] * inv0, x1 = o[nt][1] * inv0;
            size_t idx = (((size_t)b * 1024 + row0) * 1024 + h * 64 + d) >> 1;
            Ch2[idx] = __floats2half2_rn(x0, x1);
        }
        {
            float x0 = o[nt][2] * inv1, x1 = o[nt][3] * inv1;
            size_t idx = (((size_t)b * 1024 + row0 + 8) * 1024 + h * 64 + d) >> 1;
            Ch2[idx] = __floats2half2_rn(x0, x1);
        }
    }
}

// ---------------------------------------------------------------------------
// Launch
// ---------------------------------------------------------------------------
extern "C" void kernel_launch(void* const* d_in, const int* in_sizes, int n_in,
                              void* d_out, int out_size)
{
    const float* w_feat = (const float*)d_in[0];
    const float* v_feat = (const float*)d_in[1];
    const float* Ww1  = (const float*)d_in[2];
    const float* bw1  = (const float*)d_in[3];
    const float* Wv1  = (const float*)d_in[4];
    const float* bv1  = (const float*)d_in[5];
    const float* Wv2  = (const float*)d_in[6];
    const float* bv2  = (const float*)d_in[7];
    const float* Wv3  = (const float*)d_in[8];
    const float* bv3  = (const float*)d_in[9];
    const float* Wv4  = (const float*)d_in[10];
    const float* bv4  = (const float*)d_in[11];
    const float* Wout = (const float*)d_in[12];
    const float* bout = (const float*)d_in[13];
    float* out = (float*)d_out;

    float *Sp, *crp, *smp, *sivp;
    cudaGetSymbolAddress((void**)&Sp,  g_S);
    cudaGetSymbolAddress((void**)&crp, g_cr);
    cudaGetSymbolAddress((void**)&smp, g_sm);
    cudaGetSymbolAddress((void**)&sivp, g_siv);

    __half *Qh, *Ql, *Kh, *Kl, *V4h, *V3h, *W1h;
    cudaGetSymbolAddress((void**)&Qh,  g_Qh);
    cudaGetSymbolAddress((void**)&Ql,  g_Ql);
    cudaGetSymbolAddress((void**)&Kh,  g_Kh);
    cudaGetSymbolAddress((void**)&Kl,  g_Kl);
    cudaGetSymbolAddress((void**)&V4h, g_V4h);
    cudaGetSymbolAddress((void**)&V3h, g_V3h);
    cudaGetSymbolAddress((void**)&W1h, g_W1h);

    __half *Ahv, *Alv, *Ahw, *Whp, *Wlp, *Chp;
    cudaGetSymbolAddress((void**)&Ahv, g_Ahv);
    cudaGetSymbolAddress((void**)&Alv, g_Alv);
    cudaGetSymbolAddress((void**)&Ahw, g_Ahw);
    cudaGetSymbolAddress((void**)&Whp, g_Wh);
    cudaGetSymbolAddress((void**)&Wlp, g_Wl);
    cudaGetSymbolAddress((void**)&Chp, g_Ch);

    cudaFuncSetAttribute(hmma_gemm_v4, cudaFuncAttributeMaxDynamicSharedMemorySize, SMEM3);
    cudaFuncSetAttribute(hmma_gemm_out, cudaFuncAttributeMaxDynamicSharedMemorySize, SMEM1);
    cudaFuncSetAttribute(cross_scores_hmma, cudaFuncAttributeMaxDynamicSharedMemorySize, XS_SMEM);
    cudaFuncSetAttribute(attn_hmma, cudaFuncAttributeMaxDynamicSharedMemorySize, ATTN_SMEM);

    // 0: all fp32->fp16 conversions in one launch
    convert_all<<<10752, 256>>>(v_feat, w_feat, Wv1, Wv2, Wv3, Wv4, Ww1, Wout,
                                Ahv, Alv, Whp, Wlp, Ahw);

    // 1: Q/K (3t) + V3/V4 (1t) + w1 (1t) projections
    hmma_gemm_v4<<<dim3(40, 32), 256, SMEM3>>>(
        Ahv, Alv, Whp, Wlp, Ahw, bv1, bv2, bv3, bv4, bw1,
        Qh, Ql, Kh, Kl, V3h, V4h, W1h);

    // 2..4: cross-attention bias path
    cross_scores_hmma<<<dim3(8, 64), 256, XS_SMEM>>>(W1h, V3h, Sp);
    cross_rowstats<<<512, 256>>>(Sp, smp, sivp);
    cross_colsum2<<<dim3(64, 4), 256>>>(Sp, smp, sivp, crp);

    // 5: flash self-attention
    attn_hmma<<<dim3(8, 64), 256, ATTN_SMEM>>>(Qh, Ql, Kh, Kl, V4h, crp, Chp);

    // 6: output projection
    hmma_gemm_out<<<dim3(8, 32), 256, SMEM1>>>(
        Chp, Whp + 5ull * 1048576, bout, out);
}